// round 9
// baseline (speedup 1.0000x reference)
#include <cuda_runtime.h>
#include <cuda_bf16.h>
#include <math.h>
#include <stdint.h>

#define SEQ 6912
#define DIM 1536
#define NH  12
#define HD  128
#define Fg  12
#define Hg  24
#define Wg  24
#define FK  288
#define EPS_NORM 1e-6f
#define CAPF (1.0f/1.000001f)

// ---------------- scratch (device globals; no runtime allocation) ----------
__device__ float g_q[SEQ * DIM];
__device__ float g_k[SEQ * DIM];
__device__ float g_v[SEQ * DIM];
__device__ float g_attn[SEQ * DIM];
__device__ __nv_bfloat16 g_xh[SEQ * DIM];
__device__ __nv_bfloat16 g_xl[SEQ * DIM];
__device__ __nv_bfloat16 g_wh[4 * DIM * DIM];
__device__ __nv_bfloat16 g_wl[4 * DIM * DIM];
__device__ float g_aL[(size_t)NH * Fg * Wg * FK * HD];
__device__ float g_Y [(size_t)NH * Fg * Wg * FK * HD];
__device__ float g_cL[(size_t)NH * Fg * Wg * FK];

// ---------------- helpers ---------------------------------------------------
__device__ __forceinline__ void cp16(uint32_t dst, const void* src) {
    asm volatile("cp.async.cg.shared.global [%0], [%1], 16;\n" :: "r"(dst), "l"(src));
}

// ---------------- pre-pass: fp32 -> bf16 hi/lo split -------------------------
__global__ __launch_bounds__(256) void split_bf16(
    const float* __restrict__ in,
    __nv_bfloat16* __restrict__ hi, __nv_bfloat16* __restrict__ lo, int n4)
{
    const int i = blockIdx.x * 256 + threadIdx.x;
    if (i >= n4) return;
    const float4 x = reinterpret_cast<const float4*>(in)[i];
    __nv_bfloat16 h0 = __float2bfloat16(x.x);
    __nv_bfloat16 h1 = __float2bfloat16(x.y);
    __nv_bfloat16 h2 = __float2bfloat16(x.z);
    __nv_bfloat16 h3 = __float2bfloat16(x.w);
    __nv_bfloat162* hp = reinterpret_cast<__nv_bfloat162*>(hi) + i * 2;
    hp[0] = __nv_bfloat162(h0, h1);
    hp[1] = __nv_bfloat162(h2, h3);
    __nv_bfloat16 l0 = __float2bfloat16(x.x - __bfloat162float(h0));
    __nv_bfloat16 l1 = __float2bfloat16(x.y - __bfloat162float(h1));
    __nv_bfloat16 l2 = __float2bfloat16(x.z - __bfloat162float(h2));
    __nv_bfloat16 l3 = __float2bfloat16(x.w - __bfloat162float(h3));
    __nv_bfloat162* lp = reinterpret_cast<__nv_bfloat162*>(lo) + i * 2;
    lp[0] = __nv_bfloat162(l0, l1);
    lp[1] = __nv_bfloat162(l2, l3);
}

// all 4 weight matrices in one launch (blockIdx.y selects matrix)
__global__ __launch_bounds__(256) void split_bf16_w4(
    const float* __restrict__ W0, const float* __restrict__ W1,
    const float* __restrict__ W2, const float* __restrict__ W3,
    __nv_bfloat16* __restrict__ hi, __nv_bfloat16* __restrict__ lo, int n4)
{
    const int t = blockIdx.y;
    const float* src = (t == 0) ? W0 : (t == 1) ? W1 : (t == 2) ? W2 : W3;
    const int i = blockIdx.x * 256 + threadIdx.x;
    if (i >= n4) return;
    const size_t off = (size_t)t * DIM * DIM;
    const float4 x = reinterpret_cast<const float4*>(src)[i];
    __nv_bfloat16 h0 = __float2bfloat16(x.x);
    __nv_bfloat16 h1 = __float2bfloat16(x.y);
    __nv_bfloat16 h2 = __float2bfloat16(x.z);
    __nv_bfloat16 h3 = __float2bfloat16(x.w);
    __nv_bfloat162* hp = reinterpret_cast<__nv_bfloat162*>(hi + off) + i * 2;
    hp[0] = __nv_bfloat162(h0, h1);
    hp[1] = __nv_bfloat162(h2, h3);
    __nv_bfloat16 l0 = __float2bfloat16(x.x - __bfloat162float(h0));
    __nv_bfloat16 l1 = __float2bfloat16(x.y - __bfloat162float(h1));
    __nv_bfloat16 l2 = __float2bfloat16(x.z - __bfloat162float(h2));
    __nv_bfloat16 l3 = __float2bfloat16(x.w - __bfloat162float(h3));
    __nv_bfloat162* lp = reinterpret_cast<__nv_bfloat162*>(lo + off) + i * 2;
    lp[0] = __nv_bfloat162(l0, l1);
    lp[1] = __nv_bfloat162(l2, l3);
}

// ---------------- bf16 split-3 tensor GEMM: out = A @ W^T + bias -------------
// A = Ah+Al, W = Bh+Bl (bf16). acc += Ah*Bh + Ah*Bl + Al*Bh  (fp32 accum).
// BM=BN=128, BK=32, 256 threads, 8 warps 2x4, warp tile 64x32, mma.m16n8k16.
#define BPAD 40                              // bf16 elems per smem row (80B)
#define BTILE (128 * BPAD)                   // bf16 elems per tile
#define GEMM_SMEM (8 * BTILE * 2)            // bytes: 4 tiles x 2 stages

__global__ __launch_bounds__(256) void gemm_bf16s(
    const __nv_bfloat16* __restrict__ Ah, const __nv_bfloat16* __restrict__ Al,
    const __nv_bfloat16* __restrict__ Bh, const __nv_bfloat16* __restrict__ Bl,
    const float* __restrict__ bias, float* __restrict__ out,
    int M, int K, int O)
{
    extern __shared__ __nv_bfloat16 sm[];
    uint32_t sb;
    asm("{ .reg .u64 t; cvta.to.shared.u64 t, %1; cvt.u32.u64 %0, t; }"
        : "=r"(sb) : "l"(sm));

    const int tid  = threadIdx.x;
    const int lane = tid & 31;
    const int warp = tid >> 5;
    const int gid  = lane >> 2;
    const int tg   = lane & 3;
    const int wm   = (warp & 1) * 64;
    const int wn   = (warp >> 1) * 32;
    const int m0   = blockIdx.y * 128;
    const int o0   = blockIdx.x * 128;

    const __nv_bfloat16* srcs[4] = {
        Ah + (size_t)m0 * K, Al + (size_t)m0 * K,
        Bh + (size_t)o0 * K, Bl + (size_t)o0 * K };

    float acc[4][4][4];
#pragma unroll
    for (int mt = 0; mt < 4; mt++)
#pragma unroll
        for (int nt = 0; nt < 4; nt++)
#pragma unroll
            for (int r = 0; r < 4; r++) acc[mt][nt][r] = 0.f;

    const int NCH = K / 32;   // 48

    // chunk loader: 4 tiles of 128 rows x 32 bf16 (64B), rows padded to BPAD
#define LOADC(S, KC) do { \
        _Pragma("unroll") \
        for (int t = 0; t < 4; t++) { \
            const __nv_bfloat16* src = srcs[t] + (KC) * 32; \
            const uint32_t dstb = sb + (((S) * 4 + t) * BTILE) * 2; \
            _Pragma("unroll") \
            for (int q = 0; q < 2; q++) { \
                const int idx = tid + q * 256; \
                const int rr = idx >> 2, qd = idx & 3; \
                cp16(dstb + (rr * BPAD + qd * 8) * 2, \
                     src + (size_t)rr * K + qd * 8); \
            } \
        } \
        asm volatile("cp.async.commit_group;\n"); \
    } while (0)

    LOADC(0, 0);

    for (int it = 0; it < NCH; ++it) {
        const int b = it & 1;
        if (it + 1 < NCH) {
            LOADC(b ^ 1, it + 1);
            asm volatile("cp.async.wait_group 1;\n");
        } else {
            asm volatile("cp.async.wait_group 0;\n");
        }
        __syncthreads();

        const __nv_bfloat16* ah_s = sm + (b * 4 + 0) * BTILE;
        const __nv_bfloat16* al_s = sm + (b * 4 + 1) * BTILE;
        const __nv_bfloat16* bh_s = sm + (b * 4 + 2) * BTILE;
        const __nv_bfloat16* bl_s = sm + (b * 4 + 3) * BTILE;

#pragma unroll
        for (int ks = 0; ks < 2; ks++) {
            const int kc = ks * 16 + tg * 2;
            uint32_t bh[4][2], bl[4][2];
#pragma unroll
            for (int nt = 0; nt < 4; nt++) {
                const int nr = wn + nt * 8 + gid;
                bh[nt][0] = *reinterpret_cast<const uint32_t*>(&bh_s[nr * BPAD + kc]);
                bh[nt][1] = *reinterpret_cast<const uint32_t*>(&bh_s[nr * BPAD + kc + 8]);
                bl[nt][0] = *reinterpret_cast<const uint32_t*>(&bl_s[nr * BPAD + kc]);
                bl[nt][1] = *reinterpret_cast<const uint32_t*>(&bl_s[nr * BPAD + kc + 8]);
            }
#pragma unroll
            for (int mt = 0; mt < 4; mt++) {
                const int mr = wm + mt * 16 + gid;
                uint32_t ah[4], al[4];
                ah[0] = *reinterpret_cast<const uint32_t*>(&ah_s[mr * BPAD + kc]);
                ah[1] = *reinterpret_cast<const uint32_t*>(&ah_s[(mr + 8) * BPAD + kc]);
                ah[2] = *reinterpret_cast<const uint32_t*>(&ah_s[mr * BPAD + kc + 8]);
                ah[3] = *reinterpret_cast<const uint32_t*>(&ah_s[(mr + 8) * BPAD + kc + 8]);
                al[0] = *reinterpret_cast<const uint32_t*>(&al_s[mr * BPAD + kc]);
                al[1] = *reinterpret_cast<const uint32_t*>(&al_s[(mr + 8) * BPAD + kc]);
                al[2] = *reinterpret_cast<const uint32_t*>(&al_s[mr * BPAD + kc + 8]);
                al[3] = *reinterpret_cast<const uint32_t*>(&al_s[(mr + 8) * BPAD + kc + 8]);
#pragma unroll
                for (int nt = 0; nt < 4; nt++) {
#define MMA16(A0,A1,A2,A3,B0,B1) \
    asm volatile( \
        "mma.sync.aligned.m16n8k16.row.col.f32.bf16.bf16.f32 " \
        "{%0,%1,%2,%3}, {%4,%5,%6,%7}, {%8,%9}, {%0,%1,%2,%3};\n" \
        : "+f"(acc[mt][nt][0]), "+f"(acc[mt][nt][1]), \
          "+f"(acc[mt][nt][2]), "+f"(acc[mt][nt][3]) \
        : "r"(A0), "r"(A1), "r"(A2), "r"(A3), "r"(B0), "r"(B1))
                    MMA16(ah[0], ah[1], ah[2], ah[3], bh[nt][0], bh[nt][1]);
                    MMA16(ah[0], ah[1], ah[2], ah[3], bl[nt][0], bl[nt][1]);
                    MMA16(al[0], al[1], al[2], al[3], bh[nt][0], bh[nt][1]);
#undef MMA16
                }
            }
        }
        __syncthreads();
    }

    // epilogue
#pragma unroll
    for (int mt = 0; mt < 4; mt++) {
        const int m = m0 + wm + mt * 16 + gid;
#pragma unroll
        for (int nt = 0; nt < 4; nt++) {
            const int o = o0 + wn + nt * 8 + tg * 2;
            const float b0 = bias[o], b1 = bias[o + 1];
            float2 v0 = make_float2(acc[mt][nt][0] + b0, acc[mt][nt][1] + b1);
            float2 v1 = make_float2(acc[mt][nt][2] + b0, acc[mt][nt][3] + b1);
            *reinterpret_cast<float2*>(&out[(size_t)m * O + o]) = v0;
            *reinterpret_cast<float2*>(&out[(size_t)(m + 8) * O + o]) = v1;
        }
    }
}

// ---------------- fused RMSNorm + 3D RoPE + scale, in-place ------------------
__global__ __launch_bounds__(256) void norm_rope(
    float* __restrict__ data, const float* __restrict__ g,
    const float* __restrict__ freqs, float scale)
{
    const int s = blockIdx.x;
    float* row = data + (size_t)s * DIM;
    const int tid = threadIdx.x;

    float ss = 0.f;
    for (int c = tid; c < DIM; c += 256) { float v = row[c]; ss += v * v; }
#pragma unroll
    for (int off = 16; off; off >>= 1) ss += __shfl_xor_sync(~0u, ss, off);
    __shared__ float red[8];
    __shared__ float s_rms;
    if ((tid & 31) == 0) red[tid >> 5] = ss;
    __syncthreads();
    if (tid == 0) {
        float t = 0.f;
#pragma unroll
        for (int i = 0; i < 8; i++) t += red[i];
        s_rms = rsqrtf(t / (float)DIM + EPS_NORM);
    }
    __syncthreads();
    const float rms = s_rms;

    const int fidx = s / (Hg * Wg);
    const int rem  = s % (Hg * Wg);
    const int hidx = rem / Wg;
    const int widx = rem % Wg;

    for (int p = tid; p < DIM / 2; p += 256) {
        const int n = p >> 6;
        const int m = p & 63;
        const int pos = (m < 22) ? fidx : (m < 43) ? hidx : widx;
        const float ang = freqs[pos * 64 + m];
        float sn, cs;
        sincosf(ang, &sn, &cs);
        const int c0 = n * HD + 2 * m;
        const float xr = row[c0]     * rms * g[c0];
        const float xi = row[c0 + 1] * rms * g[c0 + 1];
        row[c0]     = (xr * cs - xi * sn) * scale;
        row[c0 + 1] = (xr * sn + xi * cs) * scale;
    }
}

// ---------------- Stage A --------------------------------------------------
__global__ __launch_bounds__(256) void stageA()
{
    const int kb = blockIdx.x;
    const int f  = blockIdx.y;
    const int h  = blockIdx.z;

    __shared__ float Ksh[HD * 25];
    __shared__ float Vsh[HD * 25];
    __shared__ float qsh[8 * HD];

    const int tid = threadIdx.x, lane = tid & 31, w = tid >> 5;
    const int sk_base = f * (Hg * Wg) + kb * Wg;

    for (int idx = tid; idx < 24 * HD; idx += 256) {
        const int l = idx >> 7, d = idx & 127;
        const size_t gidx = (size_t)(sk_base + l) * DIM + h * HD + d;
        Ksh[d * 25 + l] = g_k[gidx];
        Vsh[d * 25 + l] = g_v[gidx];
    }
    __syncthreads();

    for (int r = w; r < Fg * Wg; r += 8) {
        const int a = r / Wg, j = r % Wg;
        const int sq = a * (Hg * Wg) + kb * Wg + j;

        const float4 q4 = *reinterpret_cast<const float4*>(
            &g_q[(size_t)sq * DIM + h * HD + lane * 4]);
        *reinterpret_cast<float4*>(&qsh[w * HD + lane * 4]) = q4;
        __syncwarp();

        float z;
        if (lane < 24) {
            float a0 = 0.f, a1 = 0.f, a2 = 0.f, a3 = 0.f;
#pragma unroll 8
            for (int d = 0; d < HD; d += 4) {
                a0 += qsh[w * HD + d]     * Ksh[(d)     * 25 + lane];
                a1 += qsh[w * HD + d + 1] * Ksh[(d + 1) * 25 + lane];
                a2 += qsh[w * HD + d + 2] * Ksh[(d + 2) * 25 + lane];
                a3 += qsh[w * HD + d + 3] * Ksh[(d + 3) * 25 + lane];
            }
            z = ((a0 + a1) + (a2 + a3)) * CAPF;
        } else {
            z = -INFINITY;
        }
        float zm = z;
#pragma unroll
        for (int off = 16; off; off >>= 1)
            zm = fmaxf(zm, __shfl_xor_sync(~0u, zm, off));
        const float e  = (lane < 24) ? expf(z - zm) : 0.f;
        const float et = (lane < 24) ? e * (z - zm) : 0.f;
        float es = e, ets = et;
#pragma unroll
        for (int off = 16; off; off >>= 1) {
            es  += __shfl_xor_sync(~0u, es, off);
            ets += __shfl_xor_sync(~0u, ets, off);
        }
        const float inv = 1.f / es;
        const float R   = e * inv;
        const float cl  = ets * inv - logf(es);

        float accA[4] = {0.f, 0.f, 0.f, 0.f};
        float accY[4] = {0.f, 0.f, 0.f, 0.f};
#pragma unroll
        for (int l = 0; l < 24; l++) {
            const float rl = __shfl_sync(~0u, R, l);
#pragma unroll
            for (int t = 0; t < 4; t++) {
                const int d = lane + 32 * t;
                accA[t] += rl * Ksh[d * 25 + l];
                accY[t] += rl * Vsh[d * 25 + l];
            }
        }

        const size_t rowbase =
            ((size_t)(h * Fg + a) * Wg + j) * FK + (f * 24 + kb);
        const size_t ob = rowbase * HD;
#pragma unroll
        for (int t = 0; t < 4; t++) {
            g_aL[ob + lane + 32 * t] = accA[t];
            g_Y [ob + lane + 32 * t] = accY[t];
        }
        if (lane == 0) g_cL[rowbase] = cl;
        __syncwarp();
    }
}

// ---------------- Stage B --------------------------------------------------
__global__ __launch_bounds__(256) void stageB()
{
    const int j = blockIdx.x;
    const int a = blockIdx.y;
    const int h = blockIdx.z;

    __shared__ float Qsh[HD * 25];
    __shared__ float bLsh[FK * 25];
    __shared__ float alsh[8 * HD];
    __shared__ float red[8 * 24];
    __shared__ float msh[24], invsh[24];

    const int tid = threadIdx.x, lane = tid & 31, w = tid >> 5;

    for (int idx = tid; idx < 24 * HD; idx += 256) {
        const int i = idx >> 7, d = idx & 127;
        Qsh[d * 25 + i] =
            g_q[(size_t)(a * 576 + i * 24 + j) * DIM + h * HD + d];
    }
    __syncthreads();

    const size_t base   = (size_t)(h * Fg + a) * Wg + j;
    const size_t albase = base * FK * HD;
    const size_t clbase = base * FK;

    for (int fk = w; fk < FK; fk += 8) {
        const float4 a4 = *reinterpret_cast<const float4*>(
            &g_aL[albase + (size_t)fk * HD + lane * 4]);
        *reinterpret_cast<float4*>(&alsh[w * HD + lane * 4]) = a4;
        __syncwarp();
        if (lane < 24) {
            float b0 = 0.f, b1 = 0.f, b2 = 0.f, b3 = 0.f;
#pragma unroll 8
            for (int d = 0; d < HD; d += 4) {
                b0 += alsh[w * HD + d]     * Qsh[(d)     * 25 + lane];
                b1 += alsh[w * HD + d + 1] * Qsh[(d + 1) * 25 + lane];
                b2 += alsh[w * HD + d + 2] * Qsh[(d + 2) * 25 + lane];
                b3 += alsh[w * HD + d + 3] * Qsh[(d + 3) * 25 + lane];
            }
            bLsh[fk * 25 + lane] = ((b0 + b1) + (b2 + b3)) - g_cL[clbase + fk];
        }
        __syncwarp();
    }
    __syncthreads();

    const int gi = tid % 24, gg = tid / 24;
    if (tid < 192) {
        float pm = -INFINITY;
        for (int q = 0; q < 36; q++)
            pm = fmaxf(pm, bLsh[(gg * 36 + q) * 25 + gi]);
        red[gg * 24 + gi] = pm;
    }
    __syncthreads();
    if (tid < 24) {
        float m = -INFINITY;
#pragma unroll
        for (int q = 0; q < 8; q++) m = fmaxf(m, red[q * 24 + tid]);
        msh[tid] = m;
    }
    __syncthreads();
    if (tid < 192) {
        const float m = msh[gi];
        float s = 0.f;
        for (int q = 0; q < 36; q++) {
            const int fk = gg * 36 + q;
            const float e = expf(bLsh[fk * 25 + gi] - m);
            bLsh[fk * 25 + gi] = e;
            s += e;
        }
        red[gg * 24 + gi] = s;
    }
    __syncthreads();
    if (tid < 24) {
        float s = 0.f;
#pragma unroll
        for (int q = 0; q < 8; q++) s += red[q * 24 + tid];
        invsh[tid] = 1.f / s;
    }
    __syncthreads();
    for (int idx = tid; idx < FK * 24; idx += 256) {
        const int fk = idx / 24, i = idx % 24;
        bLsh[fk * 25 + i] *= invsh[i];
    }
    __syncthreads();

    // phase 3 with 4-way fk unroll for MLP on the g_Y stream
    const int d  = tid & 127;
    const int ih = (tid >> 7) * 12;
    const float* Yp = g_Y + albase + d;
    float acc[12];
#pragma unroll
    for (int ii = 0; ii < 12; ii++) acc[ii] = 0.f;
    for (int fk = 0; fk < FK; fk += 4) {
        const float y0 = Yp[(size_t)(fk + 0) * HD];
        const float y1 = Yp[(size_t)(fk + 1) * HD];
        const float y2 = Yp[(size_t)(fk + 2) * HD];
        const float y3 = Yp[(size_t)(fk + 3) * HD];
#pragma unroll
        for (int ii = 0; ii < 12; ii++) {
            acc[ii] += bLsh[(fk + 0) * 25 + ih + ii] * y0
                     + bLsh[(fk + 1) * 25 + ih + ii] * y1
                     + bLsh[(fk + 2) * 25 + ih + ii] * y2
                     + bLsh[(fk + 3) * 25 + ih + ii] * y3;
        }
    }
#pragma unroll
    for (int ii = 0; ii < 12; ii++) {
        const int i = ih + ii;
        g_attn[(size_t)(a * 576 + i * 24 + j) * DIM + h * HD + d] = acc[ii];
    }
}

// ---------------- launch --------------------------------------------------
extern "C" void kernel_launch(void* const* d_in, const int* in_sizes, int n_in,
                              void* d_out, int out_size)
{
    (void)in_sizes; (void)n_in; (void)out_size;
    const float* x  = (const float*)d_in[0];
    const float* Wq = (const float*)d_in[1];
    const float* bq = (const float*)d_in[2];
    const float* Wk = (const float*)d_in[3];
    const float* bk = (const float*)d_in[4];
    const float* Wv = (const float*)d_in[5];
    const float* bv = (const float*)d_in[6];
    const float* Wo = (const float*)d_in[7];
    const float* bo = (const float*)d_in[8];
    const float* gq = (const float*)d_in[9];
    const float* gk = (const float*)d_in[10];
    const float* fr = (const float*)d_in[11];
    float* out = (float*)d_out;

    float *qp, *kp, *vp, *ap;
    __nv_bfloat16 *xh, *xl, *wh, *wl;
    cudaGetSymbolAddress((void**)&qp, g_q);
    cudaGetSymbolAddress((void**)&kp, g_k);
    cudaGetSymbolAddress((void**)&vp, g_v);
    cudaGetSymbolAddress((void**)&ap, g_attn);
    cudaGetSymbolAddress((void**)&xh, g_xh);
    cudaGetSymbolAddress((void**)&xl, g_xl);
    cudaGetSymbolAddress((void**)&wh, g_wh);
    cudaGetSymbolAddress((void**)&wl, g_wl);

    cudaFuncSetAttribute(gemm_bf16s,
        cudaFuncAttributeMaxDynamicSharedMemorySize, GEMM_SMEM);

    const int nx4 = SEQ * DIM / 4;
    const int nw4 = DIM * DIM / 4;
    const int WSZ = DIM * DIM;

    // launch order chosen so ncu's capture window (~index 3-4) hits a GEMM
    split_bf16<<<(nx4 + 255) / 256, 256>>>(x, xh, xl, nx4);                       // 0
    split_bf16_w4<<<dim3((nw4 + 255) / 256, 4), 256>>>(Wq, Wk, Wv, Wo,
                                                       wh, wl, nw4);              // 1

    const dim3 gg(DIM / 128, SEQ / 128);   // (12, 54)
    gemm_bf16s<<<gg, 256, GEMM_SMEM>>>(xh, xl, wh + 0 * WSZ, wl + 0 * WSZ,
                                       bq, qp, SEQ, DIM, DIM);                    // 2
    gemm_bf16s<<<gg, 256, GEMM_SMEM>>>(xh, xl, wh + 1 * WSZ, wl + 1 * WSZ,
                                       bk, kp, SEQ, DIM, DIM);                    // 3
    gemm_bf16s<<<gg, 256, GEMM_SMEM>>>(xh, xl, wh + 2 * WSZ, wl + 2 * WSZ,
                                       bv, vp, SEQ, DIM, DIM);                    // 4

    const float s4 = powf((float)HD, -0.25f);
    norm_rope<<<SEQ, 256>>>(qp, gq, fr, s4);                                      // 5
    norm_rope<<<SEQ, 256>>>(kp, gk, fr, s4);                                      // 6

    stageA<<<dim3(24, 12, 12), 256>>>();                                          // 7
    stageB<<<dim3(24, 12, 12), 256>>>();                                          // 8

    split_bf16<<<(nx4 + 255) / 256, 256>>>(ap, xh, xl, nx4);                      // 9
    gemm_bf16s<<<gg, 256, GEMM_SMEM>>>(xh, xl, wh + 3 * WSZ, wl + 3 * WSZ,
                                       bo, out, SEQ, DIM, DIM);                   // 10
}

// round 10
// speedup vs baseline: 1.1758x; 1.1758x over previous
#include <cuda_runtime.h>
#include <math.h>
#include <stdint.h>

#define SEQ 6912
#define DIM 1536
#define NH  12
#define HD  128
#define Fg  12
#define Hg  24
#define Wg  24
#define FK  288
#define EPS_NORM 1e-6f
#define CAPF (1.0f/1.000001f)
#define KS  132                     // row stride for stage smem tiles

// ---------------- scratch (device globals; no runtime allocation) ----------
__device__ float g_q[SEQ * DIM];
__device__ float g_k[SEQ * DIM];
__device__ float g_v[SEQ * DIM];
__device__ float g_attn[SEQ * DIM];
__device__ float g_xr[SEQ * DIM];          // tf32-rounded, k-permuted activations
__device__ float g_w4[4 * DIM * DIM];      // tf32-rounded, k-permuted weights
__device__ float g_aL[(size_t)NH * Fg * Wg * FK * HD];
__device__ float g_Y [(size_t)NH * Fg * Wg * FK * HD];
__device__ float g_cL[(size_t)NH * Fg * Wg * FK];

// ---------------- helpers ---------------------------------------------------
__device__ __forceinline__ void cp16(void* dst, const void* src) {
    uint32_t d = (uint32_t)__cvta_generic_to_shared(dst);
    asm volatile("cp.async.cg.shared.global [%0], [%1], 16;\n" :: "r"(d), "l"(src));
}
__device__ __forceinline__ float tf32f(float x) {
    uint32_t r;
    asm("cvt.rna.tf32.f32 %0, %1;\n" : "=r"(r) : "f"(x));
    return __uint_as_float(r);
}

// ---------------- pre-pass: tf32 RNA rounding + k-permutation ---------------
// Within each 8-elem k-group -> [o0,o4,o1,o5,o2,o6,o3,o7]: mma fragment pairs
// (tg, tg+4) become adjacent -> LDS.64 in the GEMM mainloop.
__global__ __launch_bounds__(256) void round_permute(
    const float* __restrict__ in, float* __restrict__ out, int n8)
{
    const int i = blockIdx.x * 256 + threadIdx.x;
    if (i >= n8) return;
    const float4* p = reinterpret_cast<const float4*>(in) + (size_t)i * 2;
    const float4 x0 = p[0], x1 = p[1];
    float4 y0 = make_float4(tf32f(x0.x), tf32f(x1.x), tf32f(x0.y), tf32f(x1.y));
    float4 y1 = make_float4(tf32f(x0.z), tf32f(x1.z), tf32f(x0.w), tf32f(x1.w));
    float4* q = reinterpret_cast<float4*>(out) + (size_t)i * 2;
    q[0] = y0; q[1] = y1;
}

__global__ __launch_bounds__(256) void round_permute_w4(
    const float* __restrict__ W0, const float* __restrict__ W1,
    const float* __restrict__ W2, const float* __restrict__ W3,
    float* __restrict__ out, int n8)
{
    const int t = blockIdx.y;
    const float* src = (t == 0) ? W0 : (t == 1) ? W1 : (t == 2) ? W2 : W3;
    const int i = blockIdx.x * 256 + threadIdx.x;
    if (i >= n8) return;
    const float4* p = reinterpret_cast<const float4*>(src) + (size_t)i * 2;
    const float4 x0 = p[0], x1 = p[1];
    float4 y0 = make_float4(tf32f(x0.x), tf32f(x1.x), tf32f(x0.y), tf32f(x1.y));
    float4 y1 = make_float4(tf32f(x0.z), tf32f(x1.z), tf32f(x0.w), tf32f(x1.w));
    float4* q = reinterpret_cast<float4*>(out + (size_t)t * DIM * DIM)
                + (size_t)i * 2;
    q[0] = y0; q[1] = y1;
}

// ---------------- tf32 tensor-core GEMM: out = A @ W^T + bias ---------------
#define PAD 24
__global__ __launch_bounds__(256) void gemm_tf32p(
    const float* __restrict__ A, const float* __restrict__ W,
    const float* __restrict__ bias, float* __restrict__ out,
    int M, int K, int O)
{
    __shared__ float As[2][128 * PAD];
    __shared__ float Ws[2][128 * PAD];

    const int tid  = threadIdx.x;
    const int lane = tid & 31;
    const int warp = tid >> 5;
    const int gid  = lane >> 2;
    const int tg   = lane & 3;
    const int wm   = (warp & 1) * 64;
    const int wn   = (warp >> 1) * 32;
    const int m0   = blockIdx.y * 128;
    const int o0   = blockIdx.x * 128;

    const int lrow = tid >> 2;
    const int lcol = (tid & 3) * 4;

    const float* Agp = A + (size_t)(m0 + lrow) * K + lcol;
    const float* Wgp = W + (size_t)(o0 + lrow) * K + lcol;

    float acc[4][4][4];
#pragma unroll
    for (int mt = 0; mt < 4; mt++)
#pragma unroll
        for (int nt = 0; nt < 4; nt++)
#pragma unroll
            for (int r = 0; r < 4; r++) acc[mt][nt][r] = 0.f;

    const int nIter = K / 16;

    cp16(&As[0][lrow * PAD + lcol], Agp);
    cp16(&As[0][(lrow + 64) * PAD + lcol], Agp + (size_t)64 * K);
    cp16(&Ws[0][lrow * PAD + lcol], Wgp);
    cp16(&Ws[0][(lrow + 64) * PAD + lcol], Wgp + (size_t)64 * K);
    asm volatile("cp.async.commit_group;\n");

    for (int it = 0; it < nIter; ++it) {
        if (it + 1 < nIter) {
            const int nb = (it + 1) & 1;
            const int ko = (it + 1) * 16;
            cp16(&As[nb][lrow * PAD + lcol], Agp + ko);
            cp16(&As[nb][(lrow + 64) * PAD + lcol], Agp + (size_t)64 * K + ko);
            cp16(&Ws[nb][lrow * PAD + lcol], Wgp + ko);
            cp16(&Ws[nb][(lrow + 64) * PAD + lcol], Wgp + (size_t)64 * K + ko);
        }
        asm volatile("cp.async.commit_group;\n");
        asm volatile("cp.async.wait_group 1;\n");
        __syncthreads();

        const float* as = As[it & 1];
        const float* ws = Ws[it & 1];
#pragma unroll
        for (int kk = 0; kk < 16; kk += 8) {
            uint32_t a[4][4], b[4][2];
#pragma unroll
            for (int mt = 0; mt < 4; mt++) {
                const int mr = wm + mt * 16 + gid;
                const float2 pa = *reinterpret_cast<const float2*>(
                    &as[mr * PAD + kk + 2 * tg]);
                const float2 pb = *reinterpret_cast<const float2*>(
                    &as[(mr + 8) * PAD + kk + 2 * tg]);
                a[mt][0] = __float_as_uint(pa.x);
                a[mt][1] = __float_as_uint(pb.x);
                a[mt][2] = __float_as_uint(pa.y);
                a[mt][3] = __float_as_uint(pb.y);
            }
#pragma unroll
            for (int nt = 0; nt < 4; nt++) {
                const int nr = wn + nt * 8 + gid;
                const float2 pw = *reinterpret_cast<const float2*>(
                    &ws[nr * PAD + kk + 2 * tg]);
                b[nt][0] = __float_as_uint(pw.x);
                b[nt][1] = __float_as_uint(pw.y);
            }
#pragma unroll
            for (int mt = 0; mt < 4; mt++)
#pragma unroll
                for (int nt = 0; nt < 4; nt++)
                    asm volatile(
                        "mma.sync.aligned.m16n8k8.row.col.f32.tf32.tf32.f32 "
                        "{%0,%1,%2,%3}, {%4,%5,%6,%7}, {%8,%9}, {%0,%1,%2,%3};\n"
                        : "+f"(acc[mt][nt][0]), "+f"(acc[mt][nt][1]),
                          "+f"(acc[mt][nt][2]), "+f"(acc[mt][nt][3])
                        : "r"(a[mt][0]), "r"(a[mt][1]), "r"(a[mt][2]), "r"(a[mt][3]),
                          "r"(b[nt][0]), "r"(b[nt][1]));
        }
        __syncthreads();
    }

#pragma unroll
    for (int mt = 0; mt < 4; mt++) {
        const int m = m0 + wm + mt * 16 + gid;
#pragma unroll
        for (int nt = 0; nt < 4; nt++) {
            const int o = o0 + wn + nt * 8 + tg * 2;
            const float b0 = bias[o], b1 = bias[o + 1];
            float2 v0 = make_float2(acc[mt][nt][0] + b0, acc[mt][nt][1] + b1);
            float2 v1 = make_float2(acc[mt][nt][2] + b0, acc[mt][nt][3] + b1);
            *reinterpret_cast<float2*>(&out[(size_t)m * O + o]) = v0;
            *reinterpret_cast<float2*>(&out[(size_t)(m + 8) * O + o]) = v1;
        }
    }
}

// ---------------- fused RMSNorm + 3D RoPE + scale (q and k in one grid) -----
__global__ __launch_bounds__(256) void norm_rope2(
    float* __restrict__ qd, float* __restrict__ kd,
    const float* __restrict__ gqv, const float* __restrict__ gkv,
    const float* __restrict__ freqs, float scale)
{
    const int s = blockIdx.x;
    float* row = (blockIdx.y ? kd : qd) + (size_t)s * DIM;
    const float* g = blockIdx.y ? gkv : gqv;
    const int tid = threadIdx.x;

    float ss = 0.f;
    for (int c = tid; c < DIM; c += 256) { float v = row[c]; ss += v * v; }
#pragma unroll
    for (int off = 16; off; off >>= 1) ss += __shfl_xor_sync(~0u, ss, off);
    __shared__ float red[8];
    __shared__ float s_rms;
    if ((tid & 31) == 0) red[tid >> 5] = ss;
    __syncthreads();
    if (tid == 0) {
        float t = 0.f;
#pragma unroll
        for (int i = 0; i < 8; i++) t += red[i];
        s_rms = rsqrtf(t / (float)DIM + EPS_NORM);
    }
    __syncthreads();
    const float rms = s_rms;

    const int fidx = s / (Hg * Wg);
    const int rem  = s % (Hg * Wg);
    const int hidx = rem / Wg;
    const int widx = rem % Wg;

    for (int p = tid; p < DIM / 2; p += 256) {
        const int n = p >> 6;
        const int m = p & 63;
        const int pos = (m < 22) ? fidx : (m < 43) ? hidx : widx;
        const float ang = freqs[pos * 64 + m];
        float sn, cs;
        sincosf(ang, &sn, &cs);
        const int c0 = n * HD + 2 * m;
        const float xr = row[c0]     * rms * g[c0];
        const float xi = row[c0 + 1] * rms * g[c0 + 1];
        row[c0]     = (xr * cs - xi * sn) * scale;
        row[c0 + 1] = (xr * sn + xi * cs) * scale;
    }
}

// ---------------- Stage A: row-major tiles, LDS.128 everywhere --------------
__global__ __launch_bounds__(256) void stageA()
{
    const int kb = blockIdx.x;
    const int f  = blockIdx.y;
    const int h  = blockIdx.z;

    __shared__ float Ksh[24 * KS];   // [l][d] row-major, stride 132
    __shared__ float Vsh[24 * KS];
    __shared__ float qsh[8 * HD];

    const int tid = threadIdx.x, lane = tid & 31, w = tid >> 5;
    const int sk_base = f * (Hg * Wg) + kb * Wg;

    for (int idx = tid; idx < 24 * 32; idx += 256) {
        const int l = idx >> 5, c4 = idx & 31;
        const size_t gidx = (size_t)(sk_base + l) * DIM + h * HD + c4 * 4;
        *reinterpret_cast<float4*>(&Ksh[l * KS + c4 * 4]) =
            *reinterpret_cast<const float4*>(&g_k[gidx]);
        *reinterpret_cast<float4*>(&Vsh[l * KS + c4 * 4]) =
            *reinterpret_cast<const float4*>(&g_v[gidx]);
    }
    __syncthreads();

    for (int r = w; r < Fg * Wg; r += 8) {
        const int a = r / Wg, j = r % Wg;
        const int sq = a * (Hg * Wg) + kb * Wg + j;

        *reinterpret_cast<float4*>(&qsh[w * HD + lane * 4]) =
            *reinterpret_cast<const float4*>(
                &g_q[(size_t)sq * DIM + h * HD + lane * 4]);
        __syncwarp();

        float z;
        if (lane < 24) {
            const float* kr = &Ksh[lane * KS];
            const float* qr = &qsh[w * HD];
            float s0 = 0.f, s1 = 0.f, s2 = 0.f, s3 = 0.f;
#pragma unroll 8
            for (int c4 = 0; c4 < 32; c4++) {
                const float4 kk = *reinterpret_cast<const float4*>(&kr[c4 * 4]);
                const float4 qq = *reinterpret_cast<const float4*>(&qr[c4 * 4]);
                s0 += qq.x * kk.x; s1 += qq.y * kk.y;
                s2 += qq.z * kk.z; s3 += qq.w * kk.w;
            }
            z = ((s0 + s1) + (s2 + s3)) * CAPF;
        } else {
            z = -INFINITY;
        }
        float zm = z;
#pragma unroll
        for (int off = 16; off; off >>= 1)
            zm = fmaxf(zm, __shfl_xor_sync(~0u, zm, off));
        const float e  = (lane < 24) ? expf(z - zm) : 0.f;
        const float et = (lane < 24) ? e * (z - zm) : 0.f;
        float es = e, ets = et;
#pragma unroll
        for (int off = 16; off; off >>= 1) {
            es  += __shfl_xor_sync(~0u, es, off);
            ets += __shfl_xor_sync(~0u, ets, off);
        }
        const float inv = 1.f / es;
        const float R   = e * inv;
        const float cl  = ets * inv - logf(es);

        // all 32 lanes: lane owns d = lane*4 .. lane*4+3
        float4 accA = make_float4(0.f, 0.f, 0.f, 0.f);
        float4 accY = make_float4(0.f, 0.f, 0.f, 0.f);
#pragma unroll
        for (int l = 0; l < 24; l++) {
            const float rl = __shfl_sync(~0u, R, l);
            const float4 kk = *reinterpret_cast<const float4*>(
                &Ksh[l * KS + lane * 4]);
            const float4 vv = *reinterpret_cast<const float4*>(
                &Vsh[l * KS + lane * 4]);
            accA.x += rl * kk.x; accA.y += rl * kk.y;
            accA.z += rl * kk.z; accA.w += rl * kk.w;
            accY.x += rl * vv.x; accY.y += rl * vv.y;
            accY.z += rl * vv.z; accY.w += rl * vv.w;
        }

        const size_t rowbase =
            ((size_t)(h * Fg + a) * Wg + j) * FK + (f * 24 + kb);
        const size_t ob = rowbase * HD;
        *reinterpret_cast<float4*>(&g_aL[ob + lane * 4]) = accA;
        *reinterpret_cast<float4*>(&g_Y [ob + lane * 4]) = accY;
        if (lane == 0) g_cL[rowbase] = cl;
        __syncwarp();
    }
}

// ---------------- Stage B: row-major Q tile, LDS.128 dot ---------------------
__global__ __launch_bounds__(256) void stageB()
{
    const int j = blockIdx.x;
    const int a = blockIdx.y;
    const int h = blockIdx.z;

    __shared__ float Qsh[24 * KS];    // [i][d] row-major
    __shared__ float bLsh[FK * 25];   // [fk][i], stride 25
    __shared__ float alsh[8 * HD];
    __shared__ float red[8 * 24];
    __shared__ float msh[24], invsh[24];

    const int tid = threadIdx.x, lane = tid & 31, w = tid >> 5;

    for (int idx = tid; idx < 24 * 32; idx += 256) {
        const int i = idx >> 5, c4 = idx & 31;
        *reinterpret_cast<float4*>(&Qsh[i * KS + c4 * 4]) =
            *reinterpret_cast<const float4*>(
                &g_q[(size_t)(a * 576 + i * 24 + j) * DIM + h * HD + c4 * 4]);
    }
    __syncthreads();

    const size_t base   = (size_t)(h * Fg + a) * Wg + j;
    const size_t albase = base * FK * HD;
    const size_t clbase = base * FK;

    for (int fk = w; fk < FK; fk += 8) {
        *reinterpret_cast<float4*>(&alsh[w * HD + lane * 4]) =
            *reinterpret_cast<const float4*>(
                &g_aL[albase + (size_t)fk * HD + lane * 4]);
        __syncwarp();
        if (lane < 24) {
            const float* qr = &Qsh[lane * KS];
            const float* ar = &alsh[w * HD];
            float s0 = 0.f, s1 = 0.f, s2 = 0.f, s3 = 0.f;
#pragma unroll 8
            for (int c4 = 0; c4 < 32; c4++) {
                const float4 qq = *reinterpret_cast<const float4*>(&qr[c4 * 4]);
                const float4 aa = *reinterpret_cast<const float4*>(&ar[c4 * 4]);
                s0 += aa.x * qq.x; s1 += aa.y * qq.y;
                s2 += aa.z * qq.z; s3 += aa.w * qq.w;
            }
            bLsh[fk * 25 + lane] =
                ((s0 + s1) + (s2 + s3)) - g_cL[clbase + fk];
        }
        __syncwarp();
    }
    __syncthreads();

    const int gi = tid % 24, gg = tid / 24;
    if (tid < 192) {
        float pm = -INFINITY;
        for (int q = 0; q < 36; q++)
            pm = fmaxf(pm, bLsh[(gg * 36 + q) * 25 + gi]);
        red[gg * 24 + gi] = pm;
    }
    __syncthreads();
    if (tid < 24) {
        float m = -INFINITY;
#pragma unroll
        for (int q = 0; q < 8; q++) m = fmaxf(m, red[q * 24 + tid]);
        msh[tid] = m;
    }
    __syncthreads();
    if (tid < 192) {
        const float m = msh[gi];
        float s = 0.f;
        for (int q = 0; q < 36; q++) {
            const int fk = gg * 36 + q;
            const float e = expf(bLsh[fk * 25 + gi] - m);
            bLsh[fk * 25 + gi] = e;
            s += e;
        }
        red[gg * 24 + gi] = s;
    }
    __syncthreads();
    if (tid < 24) {
        float s = 0.f;
#pragma unroll
        for (int q = 0; q < 8; q++) s += red[q * 24 + tid];
        invsh[tid] = 1.f / s;
    }
    __syncthreads();
    for (int idx = tid; idx < FK * 24; idx += 256) {
        const int fk = idx / 24, i = idx % 24;
        bLsh[fk * 25 + i] *= invsh[i];
    }
    __syncthreads();

    const int d  = tid & 127;
    const int ih = (tid >> 7) * 12;
    const float* Yp = g_Y + albase + d;
    float acc[12];
#pragma unroll
    for (int ii = 0; ii < 12; ii++) acc[ii] = 0.f;
    for (int fk = 0; fk < FK; fk += 4) {
        const float y0 = Yp[(size_t)(fk + 0) * HD];
        const float y1 = Yp[(size_t)(fk + 1) * HD];
        const float y2 = Yp[(size_t)(fk + 2) * HD];
        const float y3 = Yp[(size_t)(fk + 3) * HD];
#pragma unroll
        for (int ii = 0; ii < 12; ii++) {
            acc[ii] += bLsh[(fk + 0) * 25 + ih + ii] * y0
                     + bLsh[(fk + 1) * 25 + ih + ii] * y1
                     + bLsh[(fk + 2) * 25 + ih + ii] * y2
                     + bLsh[(fk + 3) * 25 + ih + ii] * y3;
        }
    }
#pragma unroll
    for (int ii = 0; ii < 12; ii++) {
        const int i = ih + ii;
        g_attn[(size_t)(a * 576 + i * 24 + j) * DIM + h * HD + d] = acc[ii];
    }
}

// ---------------- launch --------------------------------------------------
extern "C" void kernel_launch(void* const* d_in, const int* in_sizes, int n_in,
                              void* d_out, int out_size)
{
    (void)in_sizes; (void)n_in; (void)out_size;
    const float* x  = (const float*)d_in[0];
    const float* Wq = (const float*)d_in[1];
    const float* bq = (const float*)d_in[2];
    const float* Wk = (const float*)d_in[3];
    const float* bk = (const float*)d_in[4];
    const float* Wv = (const float*)d_in[5];
    const float* bv = (const float*)d_in[6];
    const float* Wo = (const float*)d_in[7];
    const float* bo = (const float*)d_in[8];
    const float* gq = (const float*)d_in[9];
    const float* gk = (const float*)d_in[10];
    const float* fr = (const float*)d_in[11];
    float* out = (float*)d_out;

    float *qp, *kp, *vp, *ap, *xr, *w4;
    cudaGetSymbolAddress((void**)&qp, g_q);
    cudaGetSymbolAddress((void**)&kp, g_k);
    cudaGetSymbolAddress((void**)&vp, g_v);
    cudaGetSymbolAddress((void**)&ap, g_attn);
    cudaGetSymbolAddress((void**)&xr, g_xr);
    cudaGetSymbolAddress((void**)&w4, g_w4);

    const int nx8 = SEQ * DIM / 8;
    const int nw8 = DIM * DIM / 8;
    const int WSZ = DIM * DIM;

    round_permute<<<(nx8 + 255) / 256, 256>>>(x, xr, nx8);
    round_permute_w4<<<dim3((nw8 + 255) / 256, 4), 256>>>(Wq, Wk, Wv, Wo,
                                                          w4, nw8);

    const dim3 gg(DIM / 128, SEQ / 128);   // (12, 54)
    gemm_tf32p<<<gg, 256>>>(xr, w4 + 0 * WSZ, bq, qp, SEQ, DIM, DIM);
    gemm_tf32p<<<gg, 256>>>(xr, w4 + 1 * WSZ, bk, kp, SEQ, DIM, DIM);
    gemm_tf32p<<<gg, 256>>>(xr, w4 + 2 * WSZ, bv, vp, SEQ, DIM, DIM);

    const float s4 = powf((float)HD, -0.25f);
    norm_rope2<<<dim3(SEQ, 2), 256>>>(qp, kp, gq, gk, fr, s4);

    stageA<<<dim3(24, 12, 12), 256>>>();
    stageB<<<dim3(24, 12, 12), 256>>>();

    round_permute<<<(nx8 + 255) / 256, 256>>>(ap, xr, nx8);
    gemm_tf32p<<<gg, 256>>>(xr, w4 + 3 * WSZ, bo, out, SEQ, DIM, DIM);
}

// round 11
// speedup vs baseline: 1.1759x; 1.0001x over previous
#include <cuda_runtime.h>
#include <math.h>
#include <stdint.h>

#define SEQ 6912
#define DIM 1536
#define NH  12
#define HD  128
#define Fg  12
#define Hg  24
#define Wg  24
#define FK  288
#define EPS_NORM 1e-6f
#define CAPF (1.0f/1.000001f)
#define KS  132                     // row stride for stage smem tiles

// ---------------- scratch (device globals; no runtime allocation) ----------
__device__ float g_q[SEQ * DIM];
__device__ float g_k[SEQ * DIM];
__device__ float g_v[SEQ * DIM];
__device__ float g_attn[SEQ * DIM];
__device__ float g_xr[SEQ * DIM];          // tf32-rounded, k-permuted activations
__device__ float g_w4[4 * DIM * DIM];      // tf32-rounded, k-permuted weights
__device__ float g_aL[(size_t)NH * Fg * Wg * FK * HD];
__device__ float g_Y [(size_t)NH * Fg * Wg * FK * HD];
__device__ float g_cL[(size_t)NH * Fg * Wg * FK];

// ---------------- helpers ---------------------------------------------------
__device__ __forceinline__ void cp16(void* dst, const void* src) {
    uint32_t d = (uint32_t)__cvta_generic_to_shared(dst);
    asm volatile("cp.async.cg.shared.global [%0], [%1], 16;\n" :: "r"(d), "l"(src));
}
__device__ __forceinline__ float tf32f(float x) {
    uint32_t r;
    asm("cvt.rna.tf32.f32 %0, %1;\n" : "=r"(r) : "f"(x));
    return __uint_as_float(r);
}

// ---------------- pre-pass: tf32 RNA rounding + k-permutation ---------------
// Within each 8-elem k-group -> [o0,o4,o1,o5,o2,o6,o3,o7]: mma fragment pairs
// (tg, tg+4) become adjacent -> LDS.64 in the GEMM mainloop.
__global__ __launch_bounds__(256) void round_permute(
    const float* __restrict__ in, float* __restrict__ out, int n8)
{
    const int i = blockIdx.x * 256 + threadIdx.x;
    if (i >= n8) return;
    const float4* p = reinterpret_cast<const float4*>(in) + (size_t)i * 2;
    const float4 x0 = p[0], x1 = p[1];
    float4 y0 = make_float4(tf32f(x0.x), tf32f(x1.x), tf32f(x0.y), tf32f(x1.y));
    float4 y1 = make_float4(tf32f(x0.z), tf32f(x1.z), tf32f(x0.w), tf32f(x1.w));
    float4* q = reinterpret_cast<float4*>(out) + (size_t)i * 2;
    q[0] = y0; q[1] = y1;
}

__global__ __launch_bounds__(256) void round_permute_w4(
    const float* __restrict__ W0, const float* __restrict__ W1,
    const float* __restrict__ W2, const float* __restrict__ W3,
    float* __restrict__ out, int n8)
{
    const int t = blockIdx.y;
    const float* src = (t == 0) ? W0 : (t == 1) ? W1 : (t == 2) ? W2 : W3;
    const int i = blockIdx.x * 256 + threadIdx.x;
    if (i >= n8) return;
    const float4* p = reinterpret_cast<const float4*>(src) + (size_t)i * 2;
    const float4 x0 = p[0], x1 = p[1];
    float4 y0 = make_float4(tf32f(x0.x), tf32f(x1.x), tf32f(x0.y), tf32f(x1.y));
    float4 y1 = make_float4(tf32f(x0.z), tf32f(x1.z), tf32f(x0.w), tf32f(x1.w));
    float4* q = reinterpret_cast<float4*>(out + (size_t)t * DIM * DIM)
                + (size_t)i * 2;
    q[0] = y0; q[1] = y1;
}

// ---------------- tf32 tensor-core GEMM: out = A @ W^T + bias ---------------
#define PAD 24
__global__ __launch_bounds__(256) void gemm_tf32p(
    const float* __restrict__ A, const float* __restrict__ W,
    const float* __restrict__ bias, float* __restrict__ out,
    int M, int K, int O)
{
    __shared__ float As[2][128 * PAD];
    __shared__ float Ws[2][128 * PAD];

    const int tid  = threadIdx.x;
    const int lane = tid & 31;
    const int warp = tid >> 5;
    const int gid  = lane >> 2;
    const int tg   = lane & 3;
    const int wm   = (warp & 1) * 64;
    const int wn   = (warp >> 1) * 32;
    const int m0   = blockIdx.y * 128;
    const int o0   = blockIdx.x * 128;

    const int lrow = tid >> 2;
    const int lcol = (tid & 3) * 4;

    const float* Agp = A + (size_t)(m0 + lrow) * K + lcol;
    const float* Wgp = W + (size_t)(o0 + lrow) * K + lcol;

    float acc[4][4][4];
#pragma unroll
    for (int mt = 0; mt < 4; mt++)
#pragma unroll
        for (int nt = 0; nt < 4; nt++)
#pragma unroll
            for (int r = 0; r < 4; r++) acc[mt][nt][r] = 0.f;

    const int nIter = K / 16;

    cp16(&As[0][lrow * PAD + lcol], Agp);
    cp16(&As[0][(lrow + 64) * PAD + lcol], Agp + (size_t)64 * K);
    cp16(&Ws[0][lrow * PAD + lcol], Wgp);
    cp16(&Ws[0][(lrow + 64) * PAD + lcol], Wgp + (size_t)64 * K);
    asm volatile("cp.async.commit_group;\n");

    for (int it = 0; it < nIter; ++it) {
        if (it + 1 < nIter) {
            const int nb = (it + 1) & 1;
            const int ko = (it + 1) * 16;
            cp16(&As[nb][lrow * PAD + lcol], Agp + ko);
            cp16(&As[nb][(lrow + 64) * PAD + lcol], Agp + (size_t)64 * K + ko);
            cp16(&Ws[nb][lrow * PAD + lcol], Wgp + ko);
            cp16(&Ws[nb][(lrow + 64) * PAD + lcol], Wgp + (size_t)64 * K + ko);
        }
        asm volatile("cp.async.commit_group;\n");
        asm volatile("cp.async.wait_group 1;\n");
        __syncthreads();

        const float* as = As[it & 1];
        const float* ws = Ws[it & 1];
#pragma unroll
        for (int kk = 0; kk < 16; kk += 8) {
            uint32_t a[4][4], b[4][2];
#pragma unroll
            for (int mt = 0; mt < 4; mt++) {
                const int mr = wm + mt * 16 + gid;
                const float2 pa = *reinterpret_cast<const float2*>(
                    &as[mr * PAD + kk + 2 * tg]);
                const float2 pb = *reinterpret_cast<const float2*>(
                    &as[(mr + 8) * PAD + kk + 2 * tg]);
                a[mt][0] = __float_as_uint(pa.x);
                a[mt][1] = __float_as_uint(pb.x);
                a[mt][2] = __float_as_uint(pa.y);
                a[mt][3] = __float_as_uint(pb.y);
            }
#pragma unroll
            for (int nt = 0; nt < 4; nt++) {
                const int nr = wn + nt * 8 + gid;
                const float2 pw = *reinterpret_cast<const float2*>(
                    &ws[nr * PAD + kk + 2 * tg]);
                b[nt][0] = __float_as_uint(pw.x);
                b[nt][1] = __float_as_uint(pw.y);
            }
#pragma unroll
            for (int mt = 0; mt < 4; mt++)
#pragma unroll
                for (int nt = 0; nt < 4; nt++)
                    asm volatile(
                        "mma.sync.aligned.m16n8k8.row.col.f32.tf32.tf32.f32 "
                        "{%0,%1,%2,%3}, {%4,%5,%6,%7}, {%8,%9}, {%0,%1,%2,%3};\n"
                        : "+f"(acc[mt][nt][0]), "+f"(acc[mt][nt][1]),
                          "+f"(acc[mt][nt][2]), "+f"(acc[mt][nt][3])
                        : "r"(a[mt][0]), "r"(a[mt][1]), "r"(a[mt][2]), "r"(a[mt][3]),
                          "r"(b[nt][0]), "r"(b[nt][1]));
        }
        __syncthreads();
    }

#pragma unroll
    for (int mt = 0; mt < 4; mt++) {
        const int m = m0 + wm + mt * 16 + gid;
#pragma unroll
        for (int nt = 0; nt < 4; nt++) {
            const int o = o0 + wn + nt * 8 + tg * 2;
            const float b0 = bias[o], b1 = bias[o + 1];
            float2 v0 = make_float2(acc[mt][nt][0] + b0, acc[mt][nt][1] + b1);
            float2 v1 = make_float2(acc[mt][nt][2] + b0, acc[mt][nt][3] + b1);
            *reinterpret_cast<float2*>(&out[(size_t)m * O + o]) = v0;
            *reinterpret_cast<float2*>(&out[(size_t)(m + 8) * O + o]) = v1;
        }
    }
}

// ---------------- fused RMSNorm + 3D RoPE + scale (q and k in one grid) -----
__global__ __launch_bounds__(256) void norm_rope2(
    float* __restrict__ qd, float* __restrict__ kd,
    const float* __restrict__ gqv, const float* __restrict__ gkv,
    const float* __restrict__ freqs, float scale)
{
    const int s = blockIdx.x;
    float* row = (blockIdx.y ? kd : qd) + (size_t)s * DIM;
    const float* g = blockIdx.y ? gkv : gqv;
    const int tid = threadIdx.x;

    float ss = 0.f;
    for (int c = tid; c < DIM; c += 256) { float v = row[c]; ss += v * v; }
#pragma unroll
    for (int off = 16; off; off >>= 1) ss += __shfl_xor_sync(~0u, ss, off);
    __shared__ float red[8];
    __shared__ float s_rms;
    if ((tid & 31) == 0) red[tid >> 5] = ss;
    __syncthreads();
    if (tid == 0) {
        float t = 0.f;
#pragma unroll
        for (int i = 0; i < 8; i++) t += red[i];
        s_rms = rsqrtf(t / (float)DIM + EPS_NORM);
    }
    __syncthreads();
    const float rms = s_rms;

    const int fidx = s / (Hg * Wg);
    const int rem  = s % (Hg * Wg);
    const int hidx = rem / Wg;
    const int widx = rem % Wg;

    for (int p = tid; p < DIM / 2; p += 256) {
        const int n = p >> 6;
        const int m = p & 63;
        const int pos = (m < 22) ? fidx : (m < 43) ? hidx : widx;
        const float ang = freqs[pos * 64 + m];
        float sn, cs;
        sincosf(ang, &sn, &cs);
        const int c0 = n * HD + 2 * m;
        const float xr = row[c0]     * rms * g[c0];
        const float xi = row[c0 + 1] * rms * g[c0 + 1];
        row[c0]     = (xr * cs - xi * sn) * scale;
        row[c0 + 1] = (xr * sn + xi * cs) * scale;
    }
}

// ---------------- Stage A: row-major tiles, LDS.128 everywhere --------------
__global__ __launch_bounds__(256) void stageA()
{
    const int kb = blockIdx.x;
    const int f  = blockIdx.y;
    const int h  = blockIdx.z;

    __shared__ float Ksh[24 * KS];   // [l][d] row-major, stride 132
    __shared__ float Vsh[24 * KS];
    __shared__ float qsh[8 * HD];

    const int tid = threadIdx.x, lane = tid & 31, w = tid >> 5;
    const int sk_base = f * (Hg * Wg) + kb * Wg;

    for (int idx = tid; idx < 24 * 32; idx += 256) {
        const int l = idx >> 5, c4 = idx & 31;
        const size_t gidx = (size_t)(sk_base + l) * DIM + h * HD + c4 * 4;
        *reinterpret_cast<float4*>(&Ksh[l * KS + c4 * 4]) =
            *reinterpret_cast<const float4*>(&g_k[gidx]);
        *reinterpret_cast<float4*>(&Vsh[l * KS + c4 * 4]) =
            *reinterpret_cast<const float4*>(&g_v[gidx]);
    }
    __syncthreads();

    for (int r = w; r < Fg * Wg; r += 8) {
        const int a = r / Wg, j = r % Wg;
        const int sq = a * (Hg * Wg) + kb * Wg + j;

        *reinterpret_cast<float4*>(&qsh[w * HD + lane * 4]) =
            *reinterpret_cast<const float4*>(
                &g_q[(size_t)sq * DIM + h * HD + lane * 4]);
        __syncwarp();

        float z;
        if (lane < 24) {
            const float* kr = &Ksh[lane * KS];
            const float* qr = &qsh[w * HD];
            float s0 = 0.f, s1 = 0.f, s2 = 0.f, s3 = 0.f;
#pragma unroll 8
            for (int c4 = 0; c4 < 32; c4++) {
                const float4 kk = *reinterpret_cast<const float4*>(&kr[c4 * 4]);
                const float4 qq = *reinterpret_cast<const float4*>(&qr[c4 * 4]);
                s0 += qq.x * kk.x; s1 += qq.y * kk.y;
                s2 += qq.z * kk.z; s3 += qq.w * kk.w;
            }
            z = ((s0 + s1) + (s2 + s3)) * CAPF;
        } else {
            z = -INFINITY;
        }
        float zm = z;
#pragma unroll
        for (int off = 16; off; off >>= 1)
            zm = fmaxf(zm, __shfl_xor_sync(~0u, zm, off));
        const float e  = (lane < 24) ? expf(z - zm) : 0.f;
        const float et = (lane < 24) ? e * (z - zm) : 0.f;
        float es = e, ets = et;
#pragma unroll
        for (int off = 16; off; off >>= 1) {
            es  += __shfl_xor_sync(~0u, es, off);
            ets += __shfl_xor_sync(~0u, ets, off);
        }
        const float inv = 1.f / es;
        const float R   = e * inv;
        const float cl  = ets * inv - logf(es);

        // all 32 lanes: lane owns d = lane*4 .. lane*4+3
        float4 accA = make_float4(0.f, 0.f, 0.f, 0.f);
        float4 accY = make_float4(0.f, 0.f, 0.f, 0.f);
#pragma unroll
        for (int l = 0; l < 24; l++) {
            const float rl = __shfl_sync(~0u, R, l);
            const float4 kk = *reinterpret_cast<const float4*>(
                &Ksh[l * KS + lane * 4]);
            const float4 vv = *reinterpret_cast<const float4*>(
                &Vsh[l * KS + lane * 4]);
            accA.x += rl * kk.x; accA.y += rl * kk.y;
            accA.z += rl * kk.z; accA.w += rl * kk.w;
            accY.x += rl * vv.x; accY.y += rl * vv.y;
            accY.z += rl * vv.z; accY.w += rl * vv.w;
        }

        const size_t rowbase =
            ((size_t)(h * Fg + a) * Wg + j) * FK + (f * 24 + kb);
        const size_t ob = rowbase * HD;
        *reinterpret_cast<float4*>(&g_aL[ob + lane * 4]) = accA;
        *reinterpret_cast<float4*>(&g_Y [ob + lane * 4]) = accY;
        if (lane == 0) g_cL[rowbase] = cl;
        __syncwarp();
    }
}

// ---------------- Stage B: row-major Q tile, LDS.128 dot ---------------------
__global__ __launch_bounds__(256) void stageB()
{
    const int j = blockIdx.x;
    const int a = blockIdx.y;
    const int h = blockIdx.z;

    __shared__ float Qsh[24 * KS];    // [i][d] row-major
    __shared__ float bLsh[FK * 25];   // [fk][i], stride 25
    __shared__ float alsh[8 * HD];
    __shared__ float red[8 * 24];
    __shared__ float msh[24], invsh[24];

    const int tid = threadIdx.x, lane = tid & 31, w = tid >> 5;

    for (int idx = tid; idx < 24 * 32; idx += 256) {
        const int i = idx >> 5, c4 = idx & 31;
        *reinterpret_cast<float4*>(&Qsh[i * KS + c4 * 4]) =
            *reinterpret_cast<const float4*>(
                &g_q[(size_t)(a * 576 + i * 24 + j) * DIM + h * HD + c4 * 4]);
    }
    __syncthreads();

    const size_t base   = (size_t)(h * Fg + a) * Wg + j;
    const size_t albase = base * FK * HD;
    const size_t clbase = base * FK;

    for (int fk = w; fk < FK; fk += 8) {
        *reinterpret_cast<float4*>(&alsh[w * HD + lane * 4]) =
            *reinterpret_cast<const float4*>(
                &g_aL[albase + (size_t)fk * HD + lane * 4]);
        __syncwarp();
        if (lane < 24) {
            const float* qr = &Qsh[lane * KS];
            const float* ar = &alsh[w * HD];
            float s0 = 0.f, s1 = 0.f, s2 = 0.f, s3 = 0.f;
#pragma unroll 8
            for (int c4 = 0; c4 < 32; c4++) {
                const float4 qq = *reinterpret_cast<const float4*>(&qr[c4 * 4]);
                const float4 aa = *reinterpret_cast<const float4*>(&ar[c4 * 4]);
                s0 += aa.x * qq.x; s1 += aa.y * qq.y;
                s2 += aa.z * qq.z; s3 += aa.w * qq.w;
            }
            bLsh[fk * 25 + lane] =
                ((s0 + s1) + (s2 + s3)) - g_cL[clbase + fk];
        }
        __syncwarp();
    }
    __syncthreads();

    const int gi = tid % 24, gg = tid / 24;
    if (tid < 192) {
        float pm = -INFINITY;
        for (int q = 0; q < 36; q++)
            pm = fmaxf(pm, bLsh[(gg * 36 + q) * 25 + gi]);
        red[gg * 24 + gi] = pm;
    }
    __syncthreads();
    if (tid < 24) {
        float m = -INFINITY;
#pragma unroll
        for (int q = 0; q < 8; q++) m = fmaxf(m, red[q * 24 + tid]);
        msh[tid] = m;
    }
    __syncthreads();
    if (tid < 192) {
        const float m = msh[gi];
        float s = 0.f;
        for (int q = 0; q < 36; q++) {
            const int fk = gg * 36 + q;
            const float e = expf(bLsh[fk * 25 + gi] - m);
            bLsh[fk * 25 + gi] = e;
            s += e;
        }
        red[gg * 24 + gi] = s;
    }
    __syncthreads();
    if (tid < 24) {
        float s = 0.f;
#pragma unroll
        for (int q = 0; q < 8; q++) s += red[q * 24 + tid];
        invsh[tid] = 1.f / s;
    }
    __syncthreads();
    for (int idx = tid; idx < FK * 24; idx += 256) {
        const int fk = idx / 24, i = idx % 24;
        bLsh[fk * 25 + i] *= invsh[i];
    }
    __syncthreads();

    const int d  = tid & 127;
    const int ih = (tid >> 7) * 12;
    const float* Yp = g_Y + albase + d;
    float acc[12];
#pragma unroll
    for (int ii = 0; ii < 12; ii++) acc[ii] = 0.f;
    for (int fk = 0; fk < FK; fk += 4) {
        const float y0 = Yp[(size_t)(fk + 0) * HD];
        const float y1 = Yp[(size_t)(fk + 1) * HD];
        const float y2 = Yp[(size_t)(fk + 2) * HD];
        const float y3 = Yp[(size_t)(fk + 3) * HD];
#pragma unroll
        for (int ii = 0; ii < 12; ii++) {
            acc[ii] += bLsh[(fk + 0) * 25 + ih + ii] * y0
                     + bLsh[(fk + 1) * 25 + ih + ii] * y1
                     + bLsh[(fk + 2) * 25 + ih + ii] * y2
                     + bLsh[(fk + 3) * 25 + ih + ii] * y3;
        }
    }
#pragma unroll
    for (int ii = 0; ii < 12; ii++) {
        const int i = ih + ii;
        g_attn[(size_t)(a * 576 + i * 24 + j) * DIM + h * HD + d] = acc[ii];
    }
}

// ---------------- launch --------------------------------------------------
extern "C" void kernel_launch(void* const* d_in, const int* in_sizes, int n_in,
                              void* d_out, int out_size)
{
    (void)in_sizes; (void)n_in; (void)out_size;
    const float* x  = (const float*)d_in[0];
    const float* Wq = (const float*)d_in[1];
    const float* bq = (const float*)d_in[2];
    const float* Wk = (const float*)d_in[3];
    const float* bk = (const float*)d_in[4];
    const float* Wv = (const float*)d_in[5];
    const float* bv = (const float*)d_in[6];
    const float* Wo = (const float*)d_in[7];
    const float* bo = (const float*)d_in[8];
    const float* gq = (const float*)d_in[9];
    const float* gk = (const float*)d_in[10];
    const float* fr = (const float*)d_in[11];
    float* out = (float*)d_out;

    float *qp, *kp, *vp, *ap, *xr, *w4;
    cudaGetSymbolAddress((void**)&qp, g_q);
    cudaGetSymbolAddress((void**)&kp, g_k);
    cudaGetSymbolAddress((void**)&vp, g_v);
    cudaGetSymbolAddress((void**)&ap, g_attn);
    cudaGetSymbolAddress((void**)&xr, g_xr);
    cudaGetSymbolAddress((void**)&w4, g_w4);

    const int nx8 = SEQ * DIM / 8;
    const int nw8 = DIM * DIM / 8;
    const int WSZ = DIM * DIM;

    round_permute<<<(nx8 + 255) / 256, 256>>>(x, xr, nx8);
    round_permute_w4<<<dim3((nw8 + 255) / 256, 4), 256>>>(Wq, Wk, Wv, Wo,
                                                          w4, nw8);

    const dim3 gg(DIM / 128, SEQ / 128);   // (12, 54)
    gemm_tf32p<<<gg, 256>>>(xr, w4 + 0 * WSZ, bq, qp, SEQ, DIM, DIM);
    gemm_tf32p<<<gg, 256>>>(xr, w4 + 1 * WSZ, bk, kp, SEQ, DIM, DIM);
    gemm_tf32p<<<gg, 256>>>(xr, w4 + 2 * WSZ, bv, vp, SEQ, DIM, DIM);

    const float s4 = powf((float)HD, -0.25f);
    norm_rope2<<<dim3(SEQ, 2), 256>>>(qp, kp, gq, gk, fr, s4);

    stageA<<<dim3(24, 12, 12), 256>>>();
    stageB<<<dim3(24, 12, 12), 256>>>();

    round_permute<<<(nx8 + 255) / 256, 256>>>(ap, xr, nx8);
    gemm_tf32p<<<gg, 256>>>(xr, w4 + 3 * WSZ, bo, out, SEQ, DIM, DIM);
}

// round 12
// speedup vs baseline: 1.6361x; 1.3913x over previous
#include <cuda_runtime.h>
#include <cuda_bf16.h>
#include <math.h>
#include <stdint.h>

#define SEQ 6912
#define DIM 1536
#define NH  12
#define HD  128
#define Fg  12
#define Hg  24
#define Wg  24
#define FK  288
#define EPS_NORM 1e-6f
#define CAPF (1.0f/1.000001f)
#define KS  132

__device__ float g_q[SEQ * DIM];
__device__ float g_k[SEQ * DIM];
__device__ float g_v[SEQ * DIM];
__device__ float g_attn[SEQ * DIM];
__device__ float g_xr[SEQ * DIM];
__device__ float g_w4[4 * DIM * DIM];
__device__ __nv_bfloat16 g_qh[SEQ * DIM], g_ql[SEQ * DIM];
__device__ __nv_bfloat16 g_kh[SEQ * DIM], g_kl[SEQ * DIM];
__device__ __nv_bfloat16 g_vh[SEQ * DIM], g_vl[SEQ * DIM];
__device__ float g_aL[(size_t)NH * Fg * Wg * FK * HD];
__device__ float g_Y [(size_t)NH * Fg * Wg * FK * HD];
__device__ float g_cL[(size_t)NH * Fg * Wg * FK];

__device__ __forceinline__ void cp16(void* dst, const void* src) {
    uint32_t d = (uint32_t)__cvta_generic_to_shared(dst);
    asm volatile("cp.async.cg.shared.global [%0], [%1], 16;\n" :: "r"(d), "l"(src));
}
__device__ __forceinline__ float tf32f(float x) {
    uint32_t r;
    asm("cvt.rna.tf32.f32 %0, %1;\n" : "=r"(r) : "f"(x));
    return __uint_as_float(r);
}
__device__ __forceinline__ uint32_t packbf(float a, float b) {
    return (uint32_t)__bfloat16_as_ushort(__float2bfloat16(a)) |
           ((uint32_t)__bfloat16_as_ushort(__float2bfloat16(b)) << 16);
}

__global__ __launch_bounds__(256) void round_permute(
    const float* __restrict__ in, float* __restrict__ out, int n8)
{
    const int i = blockIdx.x * 256 + threadIdx.x;
    if (i >= n8) return;
    const float4* p = reinterpret_cast<const float4*>(in) + (size_t)i * 2;
    const float4 x0 = p[0], x1 = p[1];
    float4 y0 = make_float4(tf32f(x0.x), tf32f(x1.x), tf32f(x0.y), tf32f(x1.y));
    float4 y1 = make_float4(tf32f(x0.z), tf32f(x1.z), tf32f(x0.w), tf32f(x1.w));
    float4* q = reinterpret_cast<float4*>(out) + (size_t)i * 2;
    q[0] = y0; q[1] = y1;
}

__global__ __launch_bounds__(256) void round_permute_w4(
    const float* __restrict__ W0, const float* __restrict__ W1,
    const float* __restrict__ W2, const float* __restrict__ W3,
    float* __restrict__ out, int n8)
{
    const int t = blockIdx.y;
    const float* src = (t == 0) ? W0 : (t == 1) ? W1 : (t == 2) ? W2 : W3;
    const int i = blockIdx.x * 256 + threadIdx.x;
    if (i >= n8) return;
    const float4* p = reinterpret_cast<const float4*>(src) + (size_t)i * 2;
    const float4 x0 = p[0], x1 = p[1];
    float4 y0 = make_float4(tf32f(x0.x), tf32f(x1.x), tf32f(x0.y), tf32f(x1.y));
    float4 y1 = make_float4(tf32f(x0.z), tf32f(x1.z), tf32f(x0.w), tf32f(x1.w));
    float4* q = reinterpret_cast<float4*>(out + (size_t)t * DIM * DIM) + (size_t)i * 2;
    q[0] = y0; q[1] = y1;
}

__global__ __launch_bounds__(256) void split_v(int n2)
{
    const int i = blockIdx.x * 256 + threadIdx.x;
    if (i >= n2) return;
    const float2 x = reinterpret_cast<const float2*>(g_v)[i];
    const __nv_bfloat16 h0 = __float2bfloat16(x.x);
    const __nv_bfloat16 h1 = __float2bfloat16(x.y);
    *reinterpret_cast<uint32_t*>(g_vh + (size_t)i * 2) =
        (uint32_t)__bfloat16_as_ushort(h0) | ((uint32_t)__bfloat16_as_ushort(h1) << 16);
    *reinterpret_cast<uint32_t*>(g_vl + (size_t)i * 2) =
        packbf(x.x - __bfloat162float(h0), x.y - __bfloat162float(h1));
}

#define PAD 24
__global__ __launch_bounds__(256) void gemm_tf32p(
    const float* __restrict__ A, const float* __restrict__ W,
    const float* __restrict__ bias, float* __restrict__ out,
    int M, int K, int O)
{
    __shared__ float As[2][128 * PAD];
    __shared__ float Ws[2][128 * PAD];
    const int tid = threadIdx.x, lane = tid & 31, warp = tid >> 5;
    const int gid = lane >> 2, tg = lane & 3;
    const int wm = (warp & 1) * 64, wn = (warp >> 1) * 32;
    const int m0 = blockIdx.y * 128, o0 = blockIdx.x * 128;
    const int lrow = tid >> 2, lcol = (tid & 3) * 4;
    const float* Agp = A + (size_t)(m0 + lrow) * K + lcol;
    const float* Wgp = W + (size_t)(o0 + lrow) * K + lcol;

    float acc[4][4][4];
#pragma unroll
    for (int mt = 0; mt < 4; mt++)
#pragma unroll
        for (int nt = 0; nt < 4; nt++)
#pragma unroll
            for (int r = 0; r < 4; r++) acc[mt][nt][r] = 0.f;

    const int nIter = K / 16;
    cp16(&As[0][lrow * PAD + lcol], Agp);
    cp16(&As[0][(lrow + 64) * PAD + lcol], Agp + (size_t)64 * K);
    cp16(&Ws[0][lrow * PAD + lcol], Wgp);
    cp16(&Ws[0][(lrow + 64) * PAD + lcol], Wgp + (size_t)64 * K);
    asm volatile("cp.async.commit_group;\n");

    for (int it = 0; it < nIter; ++it) {
        if (it + 1 < nIter) {
            const int nb = (it + 1) & 1, ko = (it + 1) * 16;
            cp16(&As[nb][lrow * PAD + lcol], Agp + ko);
            cp16(&As[nb][(lrow + 64) * PAD + lcol], Agp + (size_t)64 * K + ko);
            cp16(&Ws[nb][lrow * PAD + lcol], Wgp + ko);
            cp16(&Ws[nb][(lrow + 64) * PAD + lcol], Wgp + (size_t)64 * K + ko);
        }
        asm volatile("cp.async.commit_group;\n");
        asm volatile("cp.async.wait_group 1;\n");
        __syncthreads();
        const float* as = As[it & 1];
        const float* ws = Ws[it & 1];
#pragma unroll
        for (int kk = 0; kk < 16; kk += 8) {
            uint32_t a[4][4], b[4][2];
#pragma unroll
            for (int mt = 0; mt < 4; mt++) {
                const int mr = wm + mt * 16 + gid;
                const float2 pa = *reinterpret_cast<const float2*>(&as[mr * PAD + kk + 2 * tg]);
                const float2 pb = *reinterpret_cast<const float2*>(&as[(mr + 8) * PAD + kk + 2 * tg]);
                a[mt][0] = __float_as_uint(pa.x); a[mt][1] = __float_as_uint(pb.x);
                a[mt][2] = __float_as_uint(pa.y); a[mt][3] = __float_as_uint(pb.y);
            }
#pragma unroll
            for (int nt = 0; nt < 4; nt++) {
                const int nr = wn + nt * 8 + gid;
                const float2 pw = *reinterpret_cast<const float2*>(&ws[nr * PAD + kk + 2 * tg]);
                b[nt][0] = __float_as_uint(pw.x); b[nt][1] = __float_as_uint(pw.y);
            }
#pragma unroll
            for (int mt = 0; mt < 4; mt++)
#pragma unroll
                for (int nt = 0; nt < 4; nt++)
                    asm volatile(
                        "mma.sync.aligned.m16n8k8.row.col.f32.tf32.tf32.f32 "
                        "{%0,%1,%2,%3}, {%4,%5,%6,%7}, {%8,%9}, {%0,%1,%2,%3};\n"
                        : "+f"(acc[mt][nt][0]), "+f"(acc[mt][nt][1]),
                          "+f"(acc[mt][nt][2]), "+f"(acc[mt][nt][3])
                        : "r"(a[mt][0]), "r"(a[mt][1]), "r"(a[mt][2]), "r"(a[mt][3]),
                          "r"(b[nt][0]), "r"(b[nt][1]));
        }
        __syncthreads();
    }
#pragma unroll
    for (int mt = 0; mt < 4; mt++) {
        const int m = m0 + wm + mt * 16 + gid;
#pragma unroll
        for (int nt = 0; nt < 4; nt++) {
            const int o = o0 + wn + nt * 8 + tg * 2;
            const float b0 = bias[o], b1 = bias[o + 1];
            *reinterpret_cast<float2*>(&out[(size_t)m * O + o]) =
                make_float2(acc[mt][nt][0] + b0, acc[mt][nt][1] + b1);
            *reinterpret_cast<float2*>(&out[(size_t)(m + 8) * O + o]) =
                make_float2(acc[mt][nt][2] + b0, acc[mt][nt][3] + b1);
        }
    }
}

// RMSNorm + RoPE + scale; writes fp32 and bf16 hi/lo
__global__ __launch_bounds__(256) void norm_rope2(
    float* __restrict__ qd, float* __restrict__ kd,
    const float* __restrict__ gqv, const float* __restrict__ gkv,
    const float* __restrict__ freqs, float scale)
{
    const int s = blockIdx.x, isK = blockIdx.y;
    float* row = (isK ? kd : qd) + (size_t)s * DIM;
    __nv_bfloat16* dh = (isK ? g_kh : g_qh) + (size_t)s * DIM;
    __nv_bfloat16* dl = (isK ? g_kl : g_ql) + (size_t)s * DIM;
    const float* g = isK ? gkv : gqv;
    const int tid = threadIdx.x;

    float ss = 0.f;
    for (int c = tid; c < DIM; c += 256) { float v = row[c]; ss += v * v; }
#pragma unroll
    for (int off = 16; off; off >>= 1) ss += __shfl_xor_sync(~0u, ss, off);
    __shared__ float red[8];
    __shared__ float s_rms;
    if ((tid & 31) == 0) red[tid >> 5] = ss;
    __syncthreads();
    if (tid == 0) {
        float t = 0.f;
#pragma unroll
        for (int i = 0; i < 8; i++) t += red[i];
        s_rms = rsqrtf(t / (float)DIM + EPS_NORM);
    }
    __syncthreads();
    const float rms = s_rms;
    const int fidx = s / 576, rem = s % 576, hidx = rem / 24, widx = rem % 24;

    for (int p = tid; p < DIM / 2; p += 256) {
        const int n = p >> 6, m = p & 63;
        const int pos = (m < 22) ? fidx : (m < 43) ? hidx : widx;
        float sn, cs;
        sincosf(freqs[pos * 64 + m], &sn, &cs);
        const int c0 = n * HD + 2 * m;
        const float xr = row[c0] * rms * g[c0];
        const float xi = row[c0 + 1] * rms * g[c0 + 1];
        const float y0 = (xr * cs - xi * sn) * scale;
        const float y1 = (xr * sn + xi * cs) * scale;
        row[c0] = y0; row[c0 + 1] = y1;
        const __nv_bfloat16 h0 = __float2bfloat16(y0);
        const __nv_bfloat16 h1 = __float2bfloat16(y1);
        *reinterpret_cast<uint32_t*>(dh + c0) =
            (uint32_t)__bfloat16_as_ushort(h0) | ((uint32_t)__bfloat16_as_ushort(h1) << 16);
        *reinterpret_cast<uint32_t*>(dl + c0) =
            packbf(y0 - __bfloat162float(h0), y1 - __bfloat162float(h1));
    }
}

#define MMAB(C,A0,A1,A2,A3,B0,B1) \
    asm volatile("mma.sync.aligned.m16n8k16.row.col.f32.bf16.bf16.f32 " \
        "{%0,%1,%2,%3}, {%4,%5,%6,%7}, {%8,%9}, {%0,%1,%2,%3};\n" \
        : "+f"((C)[0]), "+f"((C)[1]), "+f"((C)[2]), "+f"((C)[3]) \
        : "r"(A0), "r"(A1), "r"(A2), "r"(A3), "r"(B0), "r"(B1))

#define SA_SMEM (16768 * 4)

// Stage A, bf16 split-3 MMA. R stays in registers (C-fragment == A-fragment layout).
__global__ __launch_bounds__(256) void stageA_mma()
{
    const int kb = blockIdx.x, f = blockIdx.y, h = blockIdx.z;
    extern __shared__ uint32_t smw[];
    uint32_t* KH = smw;            // [l][dword] 24 x 68
    uint32_t* KL = smw + 1632;
    uint32_t* VH = smw + 3264;
    uint32_t* VL = smw + 4896;
    uint32_t* TKH = smw + 6528;    // [d][lword] 128 x 20
    uint32_t* TKL = smw + 9088;
    uint32_t* TVH = smw + 11648;
    uint32_t* TVL = smw + 14208;

    const int tid = threadIdx.x, lane = tid & 31, w = tid >> 5;
    const int gid = lane >> 2, tg = lane & 3;
    const int skb = f * 576 + kb * 24;

    for (int idx = tid; idx < 24 * 64; idx += 256) {
        const int l = idx >> 6, wd = idx & 63;
        const size_t e = (size_t)(skb + l) * DIM + h * HD + wd * 2;
        KH[l * 68 + wd] = *reinterpret_cast<const uint32_t*>(g_kh + e);
        KL[l * 68 + wd] = *reinterpret_cast<const uint32_t*>(g_kl + e);
        VH[l * 68 + wd] = *reinterpret_cast<const uint32_t*>(g_vh + e);
        VL[l * 68 + wd] = *reinterpret_cast<const uint32_t*>(g_vl + e);
    }
    __syncthreads();
    {
        const ushort* sK = (const ushort*)KH;
        const ushort* sk = (const ushort*)KL;
        const ushort* sV = (const ushort*)VH;
        const ushort* sv = (const ushort*)VL;
        for (int idx = tid; idx < 128 * 12; idx += 256) {
            const int d = idx / 12, wv = idx % 12, l = 2 * wv;
            TKH[d * 20 + wv] = (uint32_t)sK[l * 136 + d] | ((uint32_t)sK[(l + 1) * 136 + d] << 16);
            TKL[d * 20 + wv] = (uint32_t)sk[l * 136 + d] | ((uint32_t)sk[(l + 1) * 136 + d] << 16);
            TVH[d * 20 + wv] = (uint32_t)sV[l * 136 + d] | ((uint32_t)sV[(l + 1) * 136 + d] << 16);
            TVL[d * 20 + wv] = (uint32_t)sv[l * 136 + d] | ((uint32_t)sv[(l + 1) * 136 + d] << 16);
        }
    }
    __syncthreads();

    for (int mt = w; mt < 18; mt += 8) {
        const int r0 = mt * 16 + gid, r1 = r0 + 8;
        const int a0i = r0 / 24, j0 = r0 - a0i * 24;
        const int a1i = r1 / 24, j1 = r1 - a1i * 24;
        const uint32_t* q0h = (const uint32_t*)(g_qh + (size_t)(a0i * 576 + kb * 24 + j0) * DIM + h * HD);
        const uint32_t* q0l = (const uint32_t*)(g_ql + (size_t)(a0i * 576 + kb * 24 + j0) * DIM + h * HD);
        const uint32_t* q1h = (const uint32_t*)(g_qh + (size_t)(a1i * 576 + kb * 24 + j1) * DIM + h * HD);
        const uint32_t* q1l = (const uint32_t*)(g_ql + (size_t)(a1i * 576 + kb * 24 + j1) * DIM + h * HD);

        float c[3][4];
#pragma unroll
        for (int nt = 0; nt < 3; nt++)
            c[nt][0] = c[nt][1] = c[nt][2] = c[nt][3] = 0.f;
#pragma unroll
        for (int kk = 0; kk < 8; kk++) {
            const int wa = kk * 8 + tg;
            const uint32_t ah0 = q0h[wa], ah1 = q1h[wa], ah2 = q0h[wa + 4], ah3 = q1h[wa + 4];
            const uint32_t al0 = q0l[wa], al1 = q1l[wa], al2 = q0l[wa + 4], al3 = q1l[wa + 4];
#pragma unroll
            for (int nt = 0; nt < 3; nt++) {
                const int nb = (nt * 8 + gid) * 68 + wa;
                const uint32_t bh0 = KH[nb], bh1 = KH[nb + 4];
                const uint32_t bl0 = KL[nb], bl1 = KL[nb + 4];
                MMAB(c[nt], ah0, ah1, ah2, ah3, bh0, bh1);
                MMAB(c[nt], ah0, ah1, ah2, ah3, bl0, bl1);
                MMAB(c[nt], al0, al1, al2, al3, bh0, bh1);
            }
        }

        float m0 = -1e30f, m1 = -1e30f;
#pragma unroll
        for (int nt = 0; nt < 3; nt++) {
#pragma unroll
            for (int r = 0; r < 4; r++) c[nt][r] *= CAPF;
            m0 = fmaxf(m0, fmaxf(c[nt][0], c[nt][1]));
            m1 = fmaxf(m1, fmaxf(c[nt][2], c[nt][3]));
        }
        m0 = fmaxf(m0, __shfl_xor_sync(~0u, m0, 1));
        m0 = fmaxf(m0, __shfl_xor_sync(~0u, m0, 2));
        m1 = fmaxf(m1, __shfl_xor_sync(~0u, m1, 1));
        m1 = fmaxf(m1, __shfl_xor_sync(~0u, m1, 2));
        float S0 = 0.f, E0 = 0.f, S1 = 0.f, E1 = 0.f, R[3][4];
#pragma unroll
        for (int nt = 0; nt < 3; nt++) {
            const float t0 = c[nt][0] - m0, t1 = c[nt][1] - m0;
            const float t2 = c[nt][2] - m1, t3 = c[nt][3] - m1;
            const float e0 = expf(t0), e1 = expf(t1), e2 = expf(t2), e3 = expf(t3);
            S0 += e0 + e1; E0 += e0 * t0 + e1 * t1;
            S1 += e2 + e3; E1 += e2 * t2 + e3 * t3;
            R[nt][0] = e0; R[nt][1] = e1; R[nt][2] = e2; R[nt][3] = e3;
        }
        S0 += __shfl_xor_sync(~0u, S0, 1); S0 += __shfl_xor_sync(~0u, S0, 2);
        E0 += __shfl_xor_sync(~0u, E0, 1); E0 += __shfl_xor_sync(~0u, E0, 2);
        S1 += __shfl_xor_sync(~0u, S1, 1); S1 += __shfl_xor_sync(~0u, S1, 2);
        E1 += __shfl_xor_sync(~0u, E1, 1); E1 += __shfl_xor_sync(~0u, E1, 2);
        const float i0 = 1.f / S0, i1 = 1.f / S1;

        const size_t rb0 = ((size_t)((h * 12 + a0i) * 24 + j0)) * FK + (f * 24 + kb);
        const size_t rb1 = ((size_t)((h * 12 + a1i) * 24 + j1)) * FK + (f * 24 + kb);
        if (tg == 0) {
            g_cL[rb0] = E0 * i0 - logf(S0);
            g_cL[rb1] = E1 * i1 - logf(S1);
        }

        uint32_t Ph[3], Pr[3], Ql[3], Qr[3];
#pragma unroll
        for (int nt = 0; nt < 3; nt++) {
            const float r00 = R[nt][0] * i0, r01 = R[nt][1] * i0;
            const float r10 = R[nt][2] * i1, r11 = R[nt][3] * i1;
            const __nv_bfloat16 h00 = __float2bfloat16(r00);
            const __nv_bfloat16 h01 = __float2bfloat16(r01);
            const __nv_bfloat16 h10 = __float2bfloat16(r10);
            const __nv_bfloat16 h11 = __float2bfloat16(r11);
            Ph[nt] = (uint32_t)__bfloat16_as_ushort(h00) | ((uint32_t)__bfloat16_as_ushort(h01) << 16);
            Pr[nt] = (uint32_t)__bfloat16_as_ushort(h10) | ((uint32_t)__bfloat16_as_ushort(h11) << 16);
            Ql[nt] = packbf(r00 - __bfloat162float(h00), r01 - __bfloat162float(h01));
            Qr[nt] = packbf(r10 - __bfloat162float(h10), r11 - __bfloat162float(h11));
        }

        const size_t ob0 = rb0 * HD, ob1 = rb1 * HD;
#pragma unroll
        for (int nt = 0; nt < 16; nt++) {
            const int nb = (nt * 8 + gid) * 20;
            float aa[4] = {0,0,0,0}, ay[4] = {0,0,0,0};
            uint32_t b0 = TKH[nb + tg], b1 = TKH[nb + 4 + tg];
            MMAB(aa, Ph[0], Pr[0], Ph[1], Pr[1], b0, b1);
            MMAB(aa, Ql[0], Qr[0], Ql[1], Qr[1], b0, b1);
            b0 = TKL[nb + tg]; b1 = TKL[nb + 4 + tg];
            MMAB(aa, Ph[0], Pr[0], Ph[1], Pr[1], b0, b1);
            b0 = TKH[nb + 8 + tg];
            MMAB(aa, Ph[2], Pr[2], 0u, 0u, b0, b0);
            MMAB(aa, Ql[2], Qr[2], 0u, 0u, b0, b0);
            b0 = TKL[nb + 8 + tg];
            MMAB(aa, Ph[2], Pr[2], 0u, 0u, b0, b0);

            b0 = TVH[nb + tg]; b1 = TVH[nb + 4 + tg];
            MMAB(ay, Ph[0], Pr[0], Ph[1], Pr[1], b0, b1);
            MMAB(ay, Ql[0], Qr[0], Ql[1], Qr[1], b0, b1);
            b0 = TVL[nb + tg]; b1 = TVL[nb + 4 + tg];
            MMAB(ay, Ph[0], Pr[0], Ph[1], Pr[1], b0, b1);
            b0 = TVH[nb + 8 + tg];
            MMAB(ay, Ph[2], Pr[2], 0u, 0u, b0, b0);
            MMAB(ay, Ql[2], Qr[2], 0u, 0u, b0, b0);
            b0 = TVL[nb + 8 + tg];
            MMAB(ay, Ph[2], Pr[2], 0u, 0u, b0, b0);

            const int co = nt * 8 + 2 * tg;
            *reinterpret_cast<float2*>(&g_aL[ob0 + co]) = make_float2(aa[0], aa[1]);
            *reinterpret_cast<float2*>(&g_aL[ob1 + co]) = make_float2(aa[2], aa[3]);
            *reinterpret_cast<float2*>(&g_Y [ob0 + co]) = make_float2(ay[0], ay[1]);
            *reinterpret_cast<float2*>(&g_Y [ob1 + co]) = make_float2(ay[2], ay[3]);
        }
    }
}

__global__ __launch_bounds__(256) void stageB()
{
    const int j = blockIdx.x, a = blockIdx.y, h = blockIdx.z;
    __shared__ float Qsh[24 * KS];
    __shared__ float bLsh[FK * 25];
    __shared__ float alsh[8 * HD];
    __shared__ float red[8 * 24];
    __shared__ float msh[24], invsh[24];
    const int tid = threadIdx.x, lane = tid & 31, w = tid >> 5;

    for (int idx = tid; idx < 24 * 32; idx += 256) {
        const int i = idx >> 5, c4 = idx & 31;
        *reinterpret_cast<float4*>(&Qsh[i * KS + c4 * 4]) =
            *reinterpret_cast<const float4*>(
                &g_q[(size_t)(a * 576 + i * 24 + j) * DIM + h * HD + c4 * 4]);
    }
    __syncthreads();

    const size_t base = (size_t)(h * Fg + a) * Wg + j;
    const size_t albase = base * FK * HD, clbase = base * FK;

    for (int fk = w; fk < FK; fk += 8) {
        *reinterpret_cast<float4*>(&alsh[w * HD + lane * 4]) =
            *reinterpret_cast<const float4*>(&g_aL[albase + (size_t)fk * HD + lane * 4]);
        __syncwarp();
        if (lane < 24) {
            const float* qr = &Qsh[lane * KS];
            const float* ar = &alsh[w * HD];
            float s0 = 0.f, s1 = 0.f, s2 = 0.f, s3 = 0.f;
#pragma unroll 8
            for (int c4 = 0; c4 < 32; c4++) {
                const float4 qq = *reinterpret_cast<const float4*>(&qr[c4 * 4]);
                const float4 aa2 = *reinterpret_cast<const float4*>(&ar[c4 * 4]);
                s0 += aa2.x * qq.x; s1 += aa2.y * qq.y;
                s2 += aa2.z * qq.z; s3 += aa2.w * qq.w;
            }
            bLsh[fk * 25 + lane] = ((s0 + s1) + (s2 + s3)) - g_cL[clbase + fk];
        }
        __syncwarp();
    }
    __syncthreads();

    const int gi = tid % 24, gg = tid / 24;
    if (tid < 192) {
        float pm = -INFINITY;
        for (int q = 0; q < 36; q++)
            pm = fmaxf(pm, bLsh[(gg * 36 + q) * 25 + gi]);
        red[gg * 24 + gi] = pm;
    }
    __syncthreads();
    if (tid < 24) {
        float m = -INFINITY;
#pragma unroll
        for (int q = 0; q < 8; q++) m = fmaxf(m, red[q * 24 + tid]);
        msh[tid] = m;
    }
    __syncthreads();
    if (tid < 192) {
        const float m = msh[gi];
        float s = 0.f;
        for (int q = 0; q < 36; q++) {
            const int fk = gg * 36 + q;
            const float e = expf(bLsh[fk * 25 + gi] - m);
            bLsh[fk * 25 + gi] = e;
            s += e;
        }
        red[gg * 24 + gi] = s;
    }
    __syncthreads();
    if (tid < 24) {
        float s = 0.f;
#pragma unroll
        for (int q = 0; q < 8; q++) s += red[q * 24 + tid];
        invsh[tid] = 1.f / s;
    }
    __syncthreads();
    for (int idx = tid; idx < FK * 24; idx += 256) {
        const int fk = idx / 24, i = idx % 24;
        bLsh[fk * 25 + i] *= invsh[i];
    }
    __syncthreads();

    const int d = tid & 127, ih = (tid >> 7) * 12;
    const float* Yp = g_Y + albase + d;
    float acc[12];
#pragma unroll
    for (int ii = 0; ii < 12; ii++) acc[ii] = 0.f;
    for (int fk = 0; fk < FK; fk += 4) {
        const float y0 = Yp[(size_t)(fk + 0) * HD];
        const float y1 = Yp[(size_t)(fk + 1) * HD];
        const float y2 = Yp[(size_t)(fk + 2) * HD];
        const float y3 = Yp[(size_t)(fk + 3) * HD];
#pragma unroll
        for (int ii = 0; ii < 12; ii++) {
            acc[ii] += bLsh[(fk + 0) * 25 + ih + ii] * y0
                     + bLsh[(fk + 1) * 25 + ih + ii] * y1
                     + bLsh[(fk + 2) * 25 + ih + ii] * y2
                     + bLsh[(fk + 3) * 25 + ih + ii] * y3;
        }
    }
#pragma unroll
    for (int ii = 0; ii < 12; ii++) {
        const int i = ih + ii;
        g_attn[(size_t)(a * 576 + i * 24 + j) * DIM + h * HD + d] = acc[ii];
    }
}

extern "C" void kernel_launch(void* const* d_in, const int* in_sizes, int n_in,
                              void* d_out, int out_size)
{
    (void)in_sizes; (void)n_in; (void)out_size;
    const float* x  = (const float*)d_in[0];
    const float* Wq = (const float*)d_in[1];
    const float* bq = (const float*)d_in[2];
    const float* Wk = (const float*)d_in[3];
    const float* bk = (const float*)d_in[4];
    const float* Wv = (const float*)d_in[5];
    const float* bv = (const float*)d_in[6];
    const float* Wo = (const float*)d_in[7];
    const float* bo = (const float*)d_in[8];
    const float* gq = (const float*)d_in[9];
    const float* gk = (const float*)d_in[10];
    const float* fr = (const float*)d_in[11];
    float* out = (float*)d_out;

    float *qp, *kp, *vp, *ap, *xr, *w4;
    cudaGetSymbolAddress((void**)&qp, g_q);
    cudaGetSymbolAddress((void**)&kp, g_k);
    cudaGetSymbolAddress((void**)&vp, g_v);
    cudaGetSymbolAddress((void**)&ap, g_attn);
    cudaGetSymbolAddress((void**)&xr, g_xr);
    cudaGetSymbolAddress((void**)&w4, g_w4);

    cudaFuncSetAttribute(stageA_mma,
        cudaFuncAttributeMaxDynamicSharedMemorySize, SA_SMEM);

    const int nx8 = SEQ * DIM / 8;
    const int nw8 = DIM * DIM / 8;
    const int WSZ = DIM * DIM;

    round_permute<<<(nx8 + 255) / 256, 256>>>(x, xr, nx8);
    round_permute_w4<<<dim3((nw8 + 255) / 256, 4), 256>>>(Wq, Wk, Wv, Wo, w4, nw8);

    const dim3 gg(DIM / 128, SEQ / 128);
    gemm_tf32p<<<gg, 256>>>(xr, w4 + 0 * WSZ, bq, qp, SEQ, DIM, DIM);
    gemm_tf32p<<<gg, 256>>>(xr, w4 + 1 * WSZ, bk, kp, SEQ, DIM, DIM);
    gemm_tf32p<<<gg, 256>>>(xr, w4 + 2 * WSZ, bv, vp, SEQ, DIM, DIM);

    const float s4 = powf((float)HD, -0.25f);
    norm_rope2<<<dim3(SEQ, 2), 256>>>(qp, kp, gq, gk, fr, s4);
    split_v<<<(SEQ * DIM / 2 + 255) / 256, 256>>>(SEQ * DIM / 2);

    stageA_mma<<<dim3(24, 12, 12), 256, SA_SMEM>>>();
    stageB<<<dim3(24, 12, 12), 256>>>();

    round_permute<<<(nx8 + 255) / 256, 256>>>(ap, xr, nx8);
    gemm_tf32p<<<gg, 256>>>(xr, w4 + 3 * WSZ, bo, out, SEQ, DIM, DIM);
}

// round 13
// speedup vs baseline: 1.7157x; 1.0487x over previous
#include <cuda_runtime.h>
#include <cuda_bf16.h>
#include <math.h>
#include <stdint.h>

#define SEQ 6912
#define DIM 1536
#define NH  12
#define HD  128
#define Fg  12
#define Hg  24
#define Wg  24
#define FK  288
#define EPS_NORM 1e-6f
#define CAPF (1.0f/1.000001f)

__device__ float g_q[SEQ * DIM];
__device__ float g_k[SEQ * DIM];
__device__ float g_v[SEQ * DIM];
__device__ float g_attn[SEQ * DIM];
__device__ float g_xr[SEQ * DIM];
__device__ float g_w4[4 * DIM * DIM];
__device__ __nv_bfloat16 g_qh[SEQ * DIM], g_ql[SEQ * DIM];
__device__ __nv_bfloat16 g_kh[SEQ * DIM], g_kl[SEQ * DIM];
__device__ __nv_bfloat16 g_vh[SEQ * DIM], g_vl[SEQ * DIM];
__device__ __nv_bfloat16 g_ah[(size_t)NH * Fg * Wg * FK * HD];
__device__ __nv_bfloat16 g_al[(size_t)NH * Fg * Wg * FK * HD];
__device__ __nv_bfloat16 g_yh[(size_t)NH * Fg * Wg * FK * HD];
__device__ __nv_bfloat16 g_yl[(size_t)NH * Fg * Wg * FK * HD];
__device__ float g_cL[(size_t)NH * Fg * Wg * FK];

__device__ __forceinline__ void cp16(void* dst, const void* src) {
    uint32_t d = (uint32_t)__cvta_generic_to_shared(dst);
    asm volatile("cp.async.cg.shared.global [%0], [%1], 16;\n" :: "r"(d), "l"(src));
}
__device__ __forceinline__ void cp16s(uint32_t dst, const void* src) {
    asm volatile("cp.async.cg.shared.global [%0], [%1], 16;\n" :: "r"(dst), "l"(src));
}
__device__ __forceinline__ float tf32f(float x) {
    uint32_t r;
    asm("cvt.rna.tf32.f32 %0, %1;\n" : "=r"(r) : "f"(x));
    return __uint_as_float(r);
}
__device__ __forceinline__ uint32_t packbf(float a, float b) {
    return (uint32_t)__bfloat16_as_ushort(__float2bfloat16(a)) |
           ((uint32_t)__bfloat16_as_ushort(__float2bfloat16(b)) << 16);
}
__device__ __forceinline__ void split2(float f0, float f1, uint32_t& hi, uint32_t& lo) {
    const __nv_bfloat16 h0 = __float2bfloat16(f0);
    const __nv_bfloat16 h1 = __float2bfloat16(f1);
    hi = (uint32_t)__bfloat16_as_ushort(h0) | ((uint32_t)__bfloat16_as_ushort(h1) << 16);
    lo = packbf(f0 - __bfloat162float(h0), f1 - __bfloat162float(h1));
}

__global__ __launch_bounds__(256) void round_permute(
    const float* __restrict__ in, float* __restrict__ out, int n8)
{
    const int i = blockIdx.x * 256 + threadIdx.x;
    if (i >= n8) return;
    const float4* p = reinterpret_cast<const float4*>(in) + (size_t)i * 2;
    const float4 x0 = p[0], x1 = p[1];
    float4 y0 = make_float4(tf32f(x0.x), tf32f(x1.x), tf32f(x0.y), tf32f(x1.y));
    float4 y1 = make_float4(tf32f(x0.z), tf32f(x1.z), tf32f(x0.w), tf32f(x1.w));
    float4* q = reinterpret_cast<float4*>(out) + (size_t)i * 2;
    q[0] = y0; q[1] = y1;
}

__global__ __launch_bounds__(256) void round_permute_w4(
    const float* __restrict__ W0, const float* __restrict__ W1,
    const float* __restrict__ W2, const float* __restrict__ W3,
    float* __restrict__ out, int n8)
{
    const int t = blockIdx.y;
    const float* src = (t == 0) ? W0 : (t == 1) ? W1 : (t == 2) ? W2 : W3;
    const int i = blockIdx.x * 256 + threadIdx.x;
    if (i >= n8) return;
    const float4* p = reinterpret_cast<const float4*>(src) + (size_t)i * 2;
    const float4 x0 = p[0], x1 = p[1];
    float4 y0 = make_float4(tf32f(x0.x), tf32f(x1.x), tf32f(x0.y), tf32f(x1.y));
    float4 y1 = make_float4(tf32f(x0.z), tf32f(x1.z), tf32f(x0.w), tf32f(x1.w));
    float4* q = reinterpret_cast<float4*>(out + (size_t)t * DIM * DIM) + (size_t)i * 2;
    q[0] = y0; q[1] = y1;
}

__global__ __launch_bounds__(256) void split_v(int n2)
{
    const int i = blockIdx.x * 256 + threadIdx.x;
    if (i >= n2) return;
    const float2 x = reinterpret_cast<const float2*>(g_v)[i];
    uint32_t hi, lo;
    split2(x.x, x.y, hi, lo);
    *reinterpret_cast<uint32_t*>(g_vh + (size_t)i * 2) = hi;
    *reinterpret_cast<uint32_t*>(g_vl + (size_t)i * 2) = lo;
}

#define PAD 24
__global__ __launch_bounds__(256) void gemm_tf32p(
    const float* __restrict__ A, const float* __restrict__ W,
    const float* __restrict__ bias, float* __restrict__ out,
    int M, int K, int O)
{
    __shared__ float As[2][128 * PAD];
    __shared__ float Ws[2][128 * PAD];
    const int tid = threadIdx.x, lane = tid & 31, warp = tid >> 5;
    const int gid = lane >> 2, tg = lane & 3;
    const int wm = (warp & 1) * 64, wn = (warp >> 1) * 32;
    const int m0 = blockIdx.y * 128, o0 = blockIdx.x * 128;
    const int lrow = tid >> 2, lcol = (tid & 3) * 4;
    const float* Agp = A + (size_t)(m0 + lrow) * K + lcol;
    const float* Wgp = W + (size_t)(o0 + lrow) * K + lcol;

    float acc[4][4][4];
#pragma unroll
    for (int mt = 0; mt < 4; mt++)
#pragma unroll
        for (int nt = 0; nt < 4; nt++)
#pragma unroll
            for (int r = 0; r < 4; r++) acc[mt][nt][r] = 0.f;

    const int nIter = K / 16;
    cp16(&As[0][lrow * PAD + lcol], Agp);
    cp16(&As[0][(lrow + 64) * PAD + lcol], Agp + (size_t)64 * K);
    cp16(&Ws[0][lrow * PAD + lcol], Wgp);
    cp16(&Ws[0][(lrow + 64) * PAD + lcol], Wgp + (size_t)64 * K);
    asm volatile("cp.async.commit_group;\n");

    for (int it = 0; it < nIter; ++it) {
        if (it + 1 < nIter) {
            const int nb = (it + 1) & 1, ko = (it + 1) * 16;
            cp16(&As[nb][lrow * PAD + lcol], Agp + ko);
            cp16(&As[nb][(lrow + 64) * PAD + lcol], Agp + (size_t)64 * K + ko);
            cp16(&Ws[nb][lrow * PAD + lcol], Wgp + ko);
            cp16(&Ws[nb][(lrow + 64) * PAD + lcol], Wgp + (size_t)64 * K + ko);
        }
        asm volatile("cp.async.commit_group;\n");
        asm volatile("cp.async.wait_group 1;\n");
        __syncthreads();
        const float* as = As[it & 1];
        const float* ws = Ws[it & 1];
#pragma unroll
        for (int kk = 0; kk < 16; kk += 8) {
            uint32_t a[4][4], b[4][2];
#pragma unroll
            for (int mt = 0; mt < 4; mt++) {
                const int mr = wm + mt * 16 + gid;
                const float2 pa = *reinterpret_cast<const float2*>(&as[mr * PAD + kk + 2 * tg]);
                const float2 pb = *reinterpret_cast<const float2*>(&as[(mr + 8) * PAD + kk + 2 * tg]);
                a[mt][0] = __float_as_uint(pa.x); a[mt][1] = __float_as_uint(pb.x);
                a[mt][2] = __float_as_uint(pa.y); a[mt][3] = __float_as_uint(pb.y);
            }
#pragma unroll
            for (int nt = 0; nt < 4; nt++) {
                const int nr = wn + nt * 8 + gid;
                const float2 pw = *reinterpret_cast<const float2*>(&ws[nr * PAD + kk + 2 * tg]);
                b[nt][0] = __float_as_uint(pw.x); b[nt][1] = __float_as_uint(pw.y);
            }
#pragma unroll
            for (int mt = 0; mt < 4; mt++)
#pragma unroll
                for (int nt = 0; nt < 4; nt++)
                    asm volatile(
                        "mma.sync.aligned.m16n8k8.row.col.f32.tf32.tf32.f32 "
                        "{%0,%1,%2,%3}, {%4,%5,%6,%7}, {%8,%9}, {%0,%1,%2,%3};\n"
                        : "+f"(acc[mt][nt][0]), "+f"(acc[mt][nt][1]),
                          "+f"(acc[mt][nt][2]), "+f"(acc[mt][nt][3])
                        : "r"(a[mt][0]), "r"(a[mt][1]), "r"(a[mt][2]), "r"(a[mt][3]),
                          "r"(b[nt][0]), "r"(b[nt][1]));
        }
        __syncthreads();
    }
#pragma unroll
    for (int mt = 0; mt < 4; mt++) {
        const int m = m0 + wm + mt * 16 + gid;
#pragma unroll
        for (int nt = 0; nt < 4; nt++) {
            const int o = o0 + wn + nt * 8 + tg * 2;
            const float b0 = bias[o], b1 = bias[o + 1];
            *reinterpret_cast<float2*>(&out[(size_t)m * O + o]) =
                make_float2(acc[mt][nt][0] + b0, acc[mt][nt][1] + b1);
            *reinterpret_cast<float2*>(&out[(size_t)(m + 8) * O + o]) =
                make_float2(acc[mt][nt][2] + b0, acc[mt][nt][3] + b1);
        }
    }
}

// RMSNorm + RoPE + scale; emits bf16 hi/lo only
__global__ __launch_bounds__(256) void norm_rope2(
    const float* __restrict__ qd, const float* __restrict__ kd,
    const float* __restrict__ gqv, const float* __restrict__ gkv,
    const float* __restrict__ freqs, float scale)
{
    const int s = blockIdx.x, isK = blockIdx.y;
    const float* row = (isK ? kd : qd) + (size_t)s * DIM;
    __nv_bfloat16* dh = (isK ? g_kh : g_qh) + (size_t)s * DIM;
    __nv_bfloat16* dl = (isK ? g_kl : g_ql) + (size_t)s * DIM;
    const float* g = isK ? gkv : gqv;
    const int tid = threadIdx.x;

    float ss = 0.f;
    for (int c = tid; c < DIM; c += 256) { float v = row[c]; ss += v * v; }
#pragma unroll
    for (int off = 16; off; off >>= 1) ss += __shfl_xor_sync(~0u, ss, off);
    __shared__ float red[8];
    __shared__ float s_rms;
    if ((tid & 31) == 0) red[tid >> 5] = ss;
    __syncthreads();
    if (tid == 0) {
        float t = 0.f;
#pragma unroll
        for (int i = 0; i < 8; i++) t += red[i];
        s_rms = rsqrtf(t / (float)DIM + EPS_NORM);
    }
    __syncthreads();
    const float rms = s_rms;
    const int fidx = s / 576, rem = s % 576, hidx = rem / 24, widx = rem % 24;

    for (int p = tid; p < DIM / 2; p += 256) {
        const int n = p >> 6, m = p & 63;
        const int pos = (m < 22) ? fidx : (m < 43) ? hidx : widx;
        float sn, cs;
        sincosf(freqs[pos * 64 + m], &sn, &cs);
        const int c0 = n * HD + 2 * m;
        const float xr = row[c0] * rms * g[c0];
        const float xi = row[c0 + 1] * rms * g[c0 + 1];
        const float y0 = (xr * cs - xi * sn) * scale;
        const float y1 = (xr * sn + xi * cs) * scale;
        uint32_t hi, lo;
        split2(y0, y1, hi, lo);
        *reinterpret_cast<uint32_t*>(dh + c0) = hi;
        *reinterpret_cast<uint32_t*>(dl + c0) = lo;
    }
}

#define MMAB(C,A0,A1,A2,A3,B0,B1) \
    asm volatile("mma.sync.aligned.m16n8k16.row.col.f32.bf16.bf16.f32 " \
        "{%0,%1,%2,%3}, {%4,%5,%6,%7}, {%8,%9}, {%0,%1,%2,%3};\n" \
        : "+f"((C)[0]), "+f"((C)[1]), "+f"((C)[2]), "+f"((C)[3]) \
        : "r"(A0), "r"(A1), "r"(A2), "r"(A3), "r"(B0), "r"(B1))

#define SA_SMEM (16768 * 4)

__global__ __launch_bounds__(256) void stageA_mma()
{
    const int kb = blockIdx.x, f = blockIdx.y, h = blockIdx.z;
    extern __shared__ uint32_t smw[];
    uint32_t* KH = smw;
    uint32_t* KL = smw + 1632;
    uint32_t* VH = smw + 3264;
    uint32_t* VL = smw + 4896;
    uint32_t* TKH = smw + 6528;
    uint32_t* TKL = smw + 9088;
    uint32_t* TVH = smw + 11648;
    uint32_t* TVL = smw + 14208;

    const int tid = threadIdx.x, lane = tid & 31, w = tid >> 5;
    const int gid = lane >> 2, tg = lane & 3;
    const int skb = f * 576 + kb * 24;

    for (int idx = tid; idx < 24 * 64; idx += 256) {
        const int l = idx >> 6, wd = idx & 63;
        const size_t e = (size_t)(skb + l) * DIM + h * HD + wd * 2;
        KH[l * 68 + wd] = *reinterpret_cast<const uint32_t*>(g_kh + e);
        KL[l * 68 + wd] = *reinterpret_cast<const uint32_t*>(g_kl + e);
        VH[l * 68 + wd] = *reinterpret_cast<const uint32_t*>(g_vh + e);
        VL[l * 68 + wd] = *reinterpret_cast<const uint32_t*>(g_vl + e);
    }
    __syncthreads();
    {
        const ushort* sK = (const ushort*)KH;
        const ushort* sk = (const ushort*)KL;
        const ushort* sV = (const ushort*)VH;
        const ushort* sv = (const ushort*)VL;
        for (int idx = tid; idx < 128 * 12; idx += 256) {
            const int d = idx / 12, wv = idx % 12, l = 2 * wv;
            TKH[d * 20 + wv] = (uint32_t)sK[l * 136 + d] | ((uint32_t)sK[(l + 1) * 136 + d] << 16);
            TKL[d * 20 + wv] = (uint32_t)sk[l * 136 + d] | ((uint32_t)sk[(l + 1) * 136 + d] << 16);
            TVH[d * 20 + wv] = (uint32_t)sV[l * 136 + d] | ((uint32_t)sV[(l + 1) * 136 + d] << 16);
            TVL[d * 20 + wv] = (uint32_t)sv[l * 136 + d] | ((uint32_t)sv[(l + 1) * 136 + d] << 16);
        }
    }
    __syncthreads();

    for (int mt = w; mt < 18; mt += 8) {
        const int r0 = mt * 16 + gid, r1 = r0 + 8;
        const int a0i = r0 / 24, j0 = r0 - a0i * 24;
        const int a1i = r1 / 24, j1 = r1 - a1i * 24;
        const uint32_t* q0h = (const uint32_t*)(g_qh + (size_t)(a0i * 576 + kb * 24 + j0) * DIM + h * HD);
        const uint32_t* q0l = (const uint32_t*)(g_ql + (size_t)(a0i * 576 + kb * 24 + j0) * DIM + h * HD);
        const uint32_t* q1h = (const uint32_t*)(g_qh + (size_t)(a1i * 576 + kb * 24 + j1) * DIM + h * HD);
        const uint32_t* q1l = (const uint32_t*)(g_ql + (size_t)(a1i * 576 + kb * 24 + j1) * DIM + h * HD);

        float c[3][4];
#pragma unroll
        for (int nt = 0; nt < 3; nt++)
            c[nt][0] = c[nt][1] = c[nt][2] = c[nt][3] = 0.f;
#pragma unroll
        for (int kk = 0; kk < 8; kk++) {
            const int wa = kk * 8 + tg;
            const uint32_t ah0 = q0h[wa], ah1 = q1h[wa], ah2 = q0h[wa + 4], ah3 = q1h[wa + 4];
            const uint32_t al0 = q0l[wa], al1 = q1l[wa], al2 = q0l[wa + 4], al3 = q1l[wa + 4];
#pragma unroll
            for (int nt = 0; nt < 3; nt++) {
                const int nb = (nt * 8 + gid) * 68 + wa;
                const uint32_t bh0 = KH[nb], bh1 = KH[nb + 4];
                const uint32_t bl0 = KL[nb], bl1 = KL[nb + 4];
                MMAB(c[nt], ah0, ah1, ah2, ah3, bh0, bh1);
                MMAB(c[nt], ah0, ah1, ah2, ah3, bl0, bl1);
                MMAB(c[nt], al0, al1, al2, al3, bh0, bh1);
            }
        }

        float m0 = -1e30f, m1 = -1e30f;
#pragma unroll
        for (int nt = 0; nt < 3; nt++) {
#pragma unroll
            for (int r = 0; r < 4; r++) c[nt][r] *= CAPF;
            m0 = fmaxf(m0, fmaxf(c[nt][0], c[nt][1]));
            m1 = fmaxf(m1, fmaxf(c[nt][2], c[nt][3]));
        }
        m0 = fmaxf(m0, __shfl_xor_sync(~0u, m0, 1));
        m0 = fmaxf(m0, __shfl_xor_sync(~0u, m0, 2));
        m1 = fmaxf(m1, __shfl_xor_sync(~0u, m1, 1));
        m1 = fmaxf(m1, __shfl_xor_sync(~0u, m1, 2));
        float S0 = 0.f, E0 = 0.f, S1 = 0.f, E1 = 0.f, R[3][4];
#pragma unroll
        for (int nt = 0; nt < 3; nt++) {
            const float t0 = c[nt][0] - m0, t1 = c[nt][1] - m0;
            const float t2 = c[nt][2] - m1, t3 = c[nt][3] - m1;
            const float e0 = expf(t0), e1 = expf(t1), e2 = expf(t2), e3 = expf(t3);
            S0 += e0 + e1; E0 += e0 * t0 + e1 * t1;
            S1 += e2 + e3; E1 += e2 * t2 + e3 * t3;
            R[nt][0] = e0; R[nt][1] = e1; R[nt][2] = e2; R[nt][3] = e3;
        }
        S0 += __shfl_xor_sync(~0u, S0, 1); S0 += __shfl_xor_sync(~0u, S0, 2);
        E0 += __shfl_xor_sync(~0u, E0, 1); E0 += __shfl_xor_sync(~0u, E0, 2);
        S1 += __shfl_xor_sync(~0u, S1, 1); S1 += __shfl_xor_sync(~0u, S1, 2);
        E1 += __shfl_xor_sync(~0u, E1, 1); E1 += __shfl_xor_sync(~0u, E1, 2);
        const float i0 = 1.f / S0, i1 = 1.f / S1;

        const size_t rb0 = ((size_t)((h * 12 + a0i) * 24 + j0)) * FK + (f * 24 + kb);
        const size_t rb1 = ((size_t)((h * 12 + a1i) * 24 + j1)) * FK + (f * 24 + kb);
        if (tg == 0) {
            g_cL[rb0] = E0 * i0 - logf(S0);
            g_cL[rb1] = E1 * i1 - logf(S1);
        }

        uint32_t Ph[3], Pr[3], Ql[3], Qr[3];
#pragma unroll
        for (int nt = 0; nt < 3; nt++) {
            split2(R[nt][0] * i0, R[nt][1] * i0, Ph[nt], Ql[nt]);
            split2(R[nt][2] * i1, R[nt][3] * i1, Pr[nt], Qr[nt]);
        }

        const size_t wb0 = rb0 * 64, wb1 = rb1 * 64;
#pragma unroll
        for (int nt = 0; nt < 16; nt++) {
            const int nb = (nt * 8 + gid) * 20;
            float aa[4] = {0,0,0,0}, ay[4] = {0,0,0,0};
            uint32_t b0 = TKH[nb + tg], b1 = TKH[nb + 4 + tg];
            MMAB(aa, Ph[0], Pr[0], Ph[1], Pr[1], b0, b1);
            MMAB(aa, Ql[0], Qr[0], Ql[1], Qr[1], b0, b1);
            b0 = TKL[nb + tg]; b1 = TKL[nb + 4 + tg];
            MMAB(aa, Ph[0], Pr[0], Ph[1], Pr[1], b0, b1);
            b0 = TKH[nb + 8 + tg];
            MMAB(aa, Ph[2], Pr[2], 0u, 0u, b0, b0);
            MMAB(aa, Ql[2], Qr[2], 0u, 0u, b0, b0);
            b0 = TKL[nb + 8 + tg];
            MMAB(aa, Ph[2], Pr[2], 0u, 0u, b0, b0);

            b0 = TVH[nb + tg]; b1 = TVH[nb + 4 + tg];
            MMAB(ay, Ph[0], Pr[0], Ph[1], Pr[1], b0, b1);
            MMAB(ay, Ql[0], Qr[0], Ql[1], Qr[1], b0, b1);
            b0 = TVL[nb + tg]; b1 = TVL[nb + 4 + tg];
            MMAB(ay, Ph[0], Pr[0], Ph[1], Pr[1], b0, b1);
            b0 = TVH[nb + 8 + tg];
            MMAB(ay, Ph[2], Pr[2], 0u, 0u, b0, b0);
            MMAB(ay, Ql[2], Qr[2], 0u, 0u, b0, b0);
            b0 = TVL[nb + 8 + tg];
            MMAB(ay, Ph[2], Pr[2], 0u, 0u, b0, b0);

            const int wi = nt * 4 + tg;
            uint32_t hi, lo;
            split2(aa[0], aa[1], hi, lo);
            ((uint32_t*)g_ah)[wb0 + wi] = hi; ((uint32_t*)g_al)[wb0 + wi] = lo;
            split2(aa[2], aa[3], hi, lo);
            ((uint32_t*)g_ah)[wb1 + wi] = hi; ((uint32_t*)g_al)[wb1 + wi] = lo;
            split2(ay[0], ay[1], hi, lo);
            ((uint32_t*)g_yh)[wb0 + wi] = hi; ((uint32_t*)g_yl)[wb0 + wi] = lo;
            split2(ay[2], ay[3], hi, lo);
            ((uint32_t*)g_yh)[wb1 + wi] = hi; ((uint32_t*)g_yl)[wb1 + wi] = lo;
        }
    }
}

// ---------------- Stage B via bf16 split-3 MMA -------------------------------
// smem word offsets
#define QHo 0
#define QLo 1632
#define CLo 3264
#define BLo 3552          // fp32 bL [24][292]
#define LmHo 10560        // packed [32][148]
#define LmLo 15296
#define Y0H 20032         // [96][68] per chunk buffer
#define Y0L 26560
#define Y1H 33088
#define Y1L 39616
#define SB_SMEM (46144 * 4)

__global__ __launch_bounds__(256) void stageB_mma()
{
    const int j = blockIdx.x, a = blockIdx.y, h = blockIdx.z;
    extern __shared__ uint32_t smw[];
    uint32_t sb;
    asm("{ .reg .u64 t; cvta.to.shared.u64 t, %1; cvt.u32.u64 %0, t; }"
        : "=r"(sb) : "l"(smw));
    float* bl = (float*)(smw + BLo);
    float* cls = (float*)(smw + CLo);

    const int tid = threadIdx.x, lane = tid & 31, w = tid >> 5;
    const int gid = lane >> 2, tg = lane & 3;
    const size_t base = (size_t)(h * 12 + a) * 24 + j;
    const size_t albase = base * FK * HD;     // bf16 elems
    const size_t clbase = base * FK;

#define LOADY(BH, BL2, C) do { \
    _Pragma("unroll") \
    for (int t5 = 0; t5 < 6; t5++) { \
        const int idx = tid + t5 * 256; \
        const int r = idx >> 4, seg = idx & 15; \
        const size_t so = albase + (size_t)((C) * 96 + r) * HD + seg * 8; \
        cp16s(sb + ((BH) + r * 68) * 4 + seg * 16, g_yh + so); \
        cp16s(sb + ((BL2) + r * 68) * 4 + seg * 16, g_yl + so); \
    } \
    asm volatile("cp.async.commit_group;\n"); \
} while (0)

    LOADY(Y0H, Y0L, 0);   // prefetch chunk 0

    // phase 0: Q hi/lo + cL into smem
    for (int idx = tid; idx < 24 * 64; idx += 256) {
        const int i = idx >> 6, wd = idx & 63;
        const size_t e = (size_t)(a * 576 + i * 24 + j) * DIM + h * HD + wd * 2;
        smw[QHo + i * 68 + wd] = *reinterpret_cast<const uint32_t*>(g_qh + e);
        smw[QLo + i * 68 + wd] = *reinterpret_cast<const uint32_t*>(g_ql + e);
    }
    for (int idx = tid; idx < FK; idx += 256) cls[idx] = g_cL[clbase + idx];
    __syncthreads();

    // phase 1: bL[fk][i] = aL·Qᵀ − cL, stored transposed as bl[i][fk]
    for (int mt = w; mt < 18; mt += 8) {
        const int fk0 = mt * 16 + gid, fk1 = fk0 + 8;
        const uint32_t* A0h = (const uint32_t*)g_ah + albase / 2 + fk0 * 64;
        const uint32_t* A0l = (const uint32_t*)g_al + albase / 2 + fk0 * 64;
        const uint32_t* A1h = (const uint32_t*)g_ah + albase / 2 + fk1 * 64;
        const uint32_t* A1l = (const uint32_t*)g_al + albase / 2 + fk1 * 64;

        float c[3][4];
#pragma unroll
        for (int nt = 0; nt < 3; nt++)
            c[nt][0] = c[nt][1] = c[nt][2] = c[nt][3] = 0.f;
#pragma unroll
        for (int kk = 0; kk < 8; kk++) {
            const int wa = kk * 8 + tg;
            const uint32_t ah0 = A0h[wa], ah1 = A1h[wa], ah2 = A0h[wa + 4], ah3 = A1h[wa + 4];
            const uint32_t al0 = A0l[wa], al1 = A1l[wa], al2 = A0l[wa + 4], al3 = A1l[wa + 4];
#pragma unroll
            for (int nt = 0; nt < 3; nt++) {
                const int nb = QHo + (nt * 8 + gid) * 68 + wa;
                const uint32_t bh0 = smw[nb], bh1 = smw[nb + 4];
                const uint32_t bl0 = smw[nb + (QLo - QHo)], bl1 = smw[nb + (QLo - QHo) + 4];
                MMAB(c[nt], ah0, ah1, ah2, ah3, bh0, bh1);
                MMAB(c[nt], ah0, ah1, ah2, ah3, bl0, bl1);
                MMAB(c[nt], al0, al1, al2, al3, bh0, bh1);
            }
        }
        const float cl0 = cls[fk0], cl1 = cls[fk1];
#pragma unroll
        for (int nt = 0; nt < 3; nt++) {
            const int i0 = nt * 8 + 2 * tg;
            bl[i0 * 292 + fk0]       = c[nt][0] - cl0;
            bl[(i0 + 1) * 292 + fk0] = c[nt][1] - cl0;
            bl[i0 * 292 + fk1]       = c[nt][2] - cl1;
            bl[(i0 + 1) * 292 + fk1] = c[nt][3] - cl1;
        }
    }
    __syncthreads();

    // phase 2: softmax over fk per i; pack Lm to bf16 hi/lo
    for (int ri = w; ri < 24; ri += 8) {
        float* rowp = bl + ri * 292;
        float v[9], mx = -INFINITY;
#pragma unroll
        for (int q = 0; q < 9; q++) { v[q] = rowp[lane + q * 32]; mx = fmaxf(mx, v[q]); }
#pragma unroll
        for (int off = 16; off; off >>= 1) mx = fmaxf(mx, __shfl_xor_sync(~0u, mx, off));
        float s = 0.f;
#pragma unroll
        for (int q = 0; q < 9; q++) { v[q] = expf(v[q] - mx); s += v[q]; }
#pragma unroll
        for (int off = 16; off; off >>= 1) s += __shfl_xor_sync(~0u, s, off);
        const float inv = 1.f / s;
#pragma unroll
        for (int q = 0; q < 9; q++) rowp[lane + q * 32] = v[q] * inv;
        __syncwarp();
        for (int w2 = lane; w2 < 144; w2 += 32) {
            const float f0 = rowp[2 * w2], f1 = rowp[2 * w2 + 1];
            uint32_t hi, lo;
            split2(f0, f1, hi, lo);
            smw[LmHo + ri * 148 + w2] = hi;
            smw[LmLo + ri * 148 + w2] = lo;
        }
    }
    __syncthreads();

    // phase 3: out = Lmᵀ·Y over 3 Y chunks (double-buffered)
    float cc[2][2][4];
#pragma unroll
    for (int m = 0; m < 2; m++)
#pragma unroll
        for (int t = 0; t < 2; t++)
#pragma unroll
            for (int r = 0; r < 4; r++) cc[m][t][r] = 0.f;

#define YCHUNK(BH, BL2, C) do { \
    _Pragma("unroll") \
    for (int kkl = 0; kkl < 6; kkl++) { \
        const int wa = ((C) * 6 + kkl) * 8 + tg; \
        uint32_t Ah[2][4], Al2[2][4]; \
        _Pragma("unroll") \
        for (int m = 0; m < 2; m++) { \
            const int rb = (m * 16 + gid) * 148, rb8 = (m * 16 + 8 + gid) * 148; \
            Ah[m][0] = smw[LmHo + rb + wa];     Ah[m][1] = smw[LmHo + rb8 + wa]; \
            Ah[m][2] = smw[LmHo + rb + wa + 4]; Ah[m][3] = smw[LmHo + rb8 + wa + 4]; \
            Al2[m][0] = smw[LmLo + rb + wa];     Al2[m][1] = smw[LmLo + rb8 + wa]; \
            Al2[m][2] = smw[LmLo + rb + wa + 4]; Al2[m][3] = smw[LmLo + rb8 + wa + 4]; \
        } \
        _Pragma("unroll") \
        for (int t = 0; t < 2; t++) { \
            const int nn = w * 2 + t; \
            const uint32_t ad = sb + ((BH) + (kkl * 16 + (lane & 15)) * 68 + nn * 4) * 4; \
            uint32_t bh0, bh1, bl0, bl1; \
            asm volatile("ldmatrix.sync.aligned.m8n8.x2.trans.shared.b16 {%0,%1}, [%2];" \
                : "=r"(bh0), "=r"(bh1) : "r"(ad)); \
            asm volatile("ldmatrix.sync.aligned.m8n8.x2.trans.shared.b16 {%0,%1}, [%2];" \
                : "=r"(bl0), "=r"(bl1) : "r"(ad + ((BL2) - (BH)) * 4)); \
            _Pragma("unroll") \
            for (int m = 0; m < 2; m++) { \
                MMAB(cc[m][t], Ah[m][0], Ah[m][1], Ah[m][2], Ah[m][3], bh0, bh1); \
                MMAB(cc[m][t], Al2[m][0], Al2[m][1], Al2[m][2], Al2[m][3], bh0, bh1); \
                MMAB(cc[m][t], Ah[m][0], Ah[m][1], Ah[m][2], Ah[m][3], bl0, bl1); \
            } \
        } \
    } \
} while (0)

    LOADY(Y1H, Y1L, 1);
    asm volatile("cp.async.wait_group 1;\n");
    __syncthreads();
    YCHUNK(Y0H, Y0L, 0);
    __syncthreads();
    LOADY(Y0H, Y0L, 2);
    asm volatile("cp.async.wait_group 1;\n");
    __syncthreads();
    YCHUNK(Y1H, Y1L, 1);
    __syncthreads();
    asm volatile("cp.async.wait_group 0;\n");
    __syncthreads();
    YCHUNK(Y0H, Y0L, 2);

    // stores: m-tile 0 rows gid, gid+8; m-tile 1 row 16+gid only
#pragma unroll
    for (int t = 0; t < 2; t++) {
        const int d0 = (w * 2 + t) * 8 + 2 * tg;
        const size_t e0 = (size_t)(a * 576 + gid * 24 + j) * DIM + h * HD + d0;
        const size_t e1 = (size_t)(a * 576 + (gid + 8) * 24 + j) * DIM + h * HD + d0;
        const size_t e2 = (size_t)(a * 576 + (gid + 16) * 24 + j) * DIM + h * HD + d0;
        *reinterpret_cast<float2*>(&g_attn[e0]) = make_float2(cc[0][t][0], cc[0][t][1]);
        *reinterpret_cast<float2*>(&g_attn[e1]) = make_float2(cc[0][t][2], cc[0][t][3]);
        *reinterpret_cast<float2*>(&g_attn[e2]) = make_float2(cc[1][t][0], cc[1][t][1]);
    }
}

extern "C" void kernel_launch(void* const* d_in, const int* in_sizes, int n_in,
                              void* d_out, int out_size)
{
    (void)in_sizes; (void)n_in; (void)out_size;
    const float* x  = (const float*)d_in[0];
    const float* Wq = (const float*)d_in[1];
    const float* bq = (const float*)d_in[2];
    const float* Wk = (const float*)d_in[3];
    const float* bk = (const float*)d_in[4];
    const float* Wv = (const float*)d_in[5];
    const float* bv = (const float*)d_in[6];
    const float* Wo = (const float*)d_in[7];
    const float* bo = (const float*)d_in[8];
    const float* gq = (const float*)d_in[9];
    const float* gk = (const float*)d_in[10];
    const float* fr = (const float*)d_in[11];
    float* out = (float*)d_out;

    float *qp, *kp, *vp, *ap, *xr, *w4;
    cudaGetSymbolAddress((void**)&qp, g_q);
    cudaGetSymbolAddress((void**)&kp, g_k);
    cudaGetSymbolAddress((void**)&vp, g_v);
    cudaGetSymbolAddress((void**)&ap, g_attn);
    cudaGetSymbolAddress((void**)&xr, g_xr);
    cudaGetSymbolAddress((void**)&w4, g_w4);

    cudaFuncSetAttribute(stageA_mma,
        cudaFuncAttributeMaxDynamicSharedMemorySize, SA_SMEM);
    cudaFuncSetAttribute(stageB_mma,
        cudaFuncAttributeMaxDynamicSharedMemorySize, SB_SMEM);

    const int nx8 = SEQ * DIM / 8;
    const int nw8 = DIM * DIM / 8;
    const int WSZ = DIM * DIM;

    round_permute<<<(nx8 + 255) / 256, 256>>>(x, xr, nx8);
    round_permute_w4<<<dim3((nw8 + 255) / 256, 4), 256>>>(Wq, Wk, Wv, Wo, w4, nw8);

    const dim3 gg(DIM / 128, SEQ / 128);
    gemm_tf32p<<<gg, 256>>>(xr, w4 + 0 * WSZ, bq, qp, SEQ, DIM, DIM);
    gemm_tf32p<<<gg, 256>>>(xr, w4 + 1 * WSZ, bk, kp, SEQ, DIM, DIM);
    gemm_tf32p<<<gg, 256>>>(xr, w4 + 2 * WSZ, bv, vp, SEQ, DIM, DIM);

    const float s4 = powf((float)HD, -0.25f);
    norm_rope2<<<dim3(SEQ, 2), 256>>>(qp, kp, gq, gk, fr, s4);
    split_v<<<(SEQ * DIM / 2 + 255) / 256, 256>>>(SEQ * DIM / 2);

    stageA_mma<<<dim3(24, 12, 12), 256, SA_SMEM>>>();
    stageB_mma<<<dim3(24, 12, 12), 256, SB_SMEM>>>();

    round_permute<<<(nx8 + 255) / 256, 256>>>(ap, xr, nx8);
    gemm_tf32p<<<gg, 256>>>(xr, w4 + 3 * WSZ, bo, out, SEQ, DIM, DIM);
}

// round 14
// speedup vs baseline: 1.7926x; 1.0449x over previous
#include <cuda_runtime.h>
#include <cuda_bf16.h>
#include <math.h>
#include <stdint.h>

#define SEQ 6912
#define DIM 1536
#define NH  12
#define HD  128
#define Fg  12
#define Hg  24
#define Wg  24
#define FK  288
#define EPS_NORM 1e-6f
#define CAPF (1.0f/1.000001f)

__device__ float g_q[SEQ * DIM];
__device__ float g_k[SEQ * DIM];
__device__ float g_v[SEQ * DIM];
__device__ float g_attn[SEQ * DIM];
__device__ float g_xr[SEQ * DIM];
__device__ float g_w4[4 * DIM * DIM];
__device__ __nv_bfloat16 g_qh[SEQ * DIM], g_ql[SEQ * DIM];
__device__ __nv_bfloat16 g_kh[SEQ * DIM], g_kl[SEQ * DIM];
__device__ __nv_bfloat16 g_vh[SEQ * DIM], g_vl[SEQ * DIM];
__device__ __nv_bfloat16 g_ah[(size_t)NH * Fg * Wg * FK * HD];
__device__ __nv_bfloat16 g_al[(size_t)NH * Fg * Wg * FK * HD];
__device__ __nv_bfloat16 g_yh[(size_t)NH * Fg * Wg * FK * HD];
__device__ __nv_bfloat16 g_yl[(size_t)NH * Fg * Wg * FK * HD];
__device__ float g_cL[(size_t)NH * Fg * Wg * FK];

__device__ __forceinline__ void cp16(void* dst, const void* src) {
    uint32_t d = (uint32_t)__cvta_generic_to_shared(dst);
    asm volatile("cp.async.cg.shared.global [%0], [%1], 16;\n" :: "r"(d), "l"(src));
}
__device__ __forceinline__ void cp16s(uint32_t dst, const void* src) {
    asm volatile("cp.async.cg.shared.global [%0], [%1], 16;\n" :: "r"(dst), "l"(src));
}
__device__ __forceinline__ float tf32f(float x) {
    uint32_t r;
    asm("cvt.rna.tf32.f32 %0, %1;\n" : "=r"(r) : "f"(x));
    return __uint_as_float(r);
}
__device__ __forceinline__ uint32_t packbf(float a, float b) {
    return (uint32_t)__bfloat16_as_ushort(__float2bfloat16(a)) |
           ((uint32_t)__bfloat16_as_ushort(__float2bfloat16(b)) << 16);
}
__device__ __forceinline__ void split2(float f0, float f1, uint32_t& hi, uint32_t& lo) {
    const __nv_bfloat16 h0 = __float2bfloat16(f0);
    const __nv_bfloat16 h1 = __float2bfloat16(f1);
    hi = (uint32_t)__bfloat16_as_ushort(h0) | ((uint32_t)__bfloat16_as_ushort(h1) << 16);
    lo = packbf(f0 - __bfloat162float(h0), f1 - __bfloat162float(h1));
}

__global__ __launch_bounds__(256) void round_permute(
    const float* __restrict__ in, float* __restrict__ out, int n8)
{
    const int i = blockIdx.x * 256 + threadIdx.x;
    if (i >= n8) return;
    const float4* p = reinterpret_cast<const float4*>(in) + (size_t)i * 2;
    const float4 x0 = p[0], x1 = p[1];
    float4 y0 = make_float4(tf32f(x0.x), tf32f(x1.x), tf32f(x0.y), tf32f(x1.y));
    float4 y1 = make_float4(tf32f(x0.z), tf32f(x1.z), tf32f(x0.w), tf32f(x1.w));
    float4* q = reinterpret_cast<float4*>(out) + (size_t)i * 2;
    q[0] = y0; q[1] = y1;
}

__global__ __launch_bounds__(256) void round_permute_w4(
    const float* __restrict__ W0, const float* __restrict__ W1,
    const float* __restrict__ W2, const float* __restrict__ W3,
    float* __restrict__ out, int n8)
{
    const int t = blockIdx.y;
    const float* src = (t == 0) ? W0 : (t == 1) ? W1 : (t == 2) ? W2 : W3;
    const int i = blockIdx.x * 256 + threadIdx.x;
    if (i >= n8) return;
    const float4* p = reinterpret_cast<const float4*>(src) + (size_t)i * 2;
    const float4 x0 = p[0], x1 = p[1];
    float4 y0 = make_float4(tf32f(x0.x), tf32f(x1.x), tf32f(x0.y), tf32f(x1.y));
    float4 y1 = make_float4(tf32f(x0.z), tf32f(x1.z), tf32f(x0.w), tf32f(x1.w));
    float4* q = reinterpret_cast<float4*>(out + (size_t)t * DIM * DIM) + (size_t)i * 2;
    q[0] = y0; q[1] = y1;
}

__global__ __launch_bounds__(256) void split_v(int n2)
{
    const int i = blockIdx.x * 256 + threadIdx.x;
    if (i >= n2) return;
    const float2 x = reinterpret_cast<const float2*>(g_v)[i];
    uint32_t hi, lo;
    split2(x.x, x.y, hi, lo);
    *reinterpret_cast<uint32_t*>(g_vh + (size_t)i * 2) = hi;
    *reinterpret_cast<uint32_t*>(g_vl + (size_t)i * 2) = lo;
}

#define PAD 24
__global__ __launch_bounds__(256) void gemm_tf32p(
    const float* __restrict__ A, const float* __restrict__ W,
    const float* __restrict__ bias, float* __restrict__ out,
    int M, int K, int O)
{
    __shared__ float As[2][128 * PAD];
    __shared__ float Ws[2][128 * PAD];
    const int tid = threadIdx.x, lane = tid & 31, warp = tid >> 5;
    const int gid = lane >> 2, tg = lane & 3;
    const int wm = (warp & 1) * 64, wn = (warp >> 1) * 32;
    const int m0 = blockIdx.y * 128, o0 = blockIdx.x * 128;
    const int lrow = tid >> 2, lcol = (tid & 3) * 4;
    const float* Agp = A + (size_t)(m0 + lrow) * K + lcol;
    const float* Wgp = W + (size_t)(o0 + lrow) * K + lcol;

    float acc[4][4][4];
#pragma unroll
    for (int mt = 0; mt < 4; mt++)
#pragma unroll
        for (int nt = 0; nt < 4; nt++)
#pragma unroll
            for (int r = 0; r < 4; r++) acc[mt][nt][r] = 0.f;

    const int nIter = K / 16;
    cp16(&As[0][lrow * PAD + lcol], Agp);
    cp16(&As[0][(lrow + 64) * PAD + lcol], Agp + (size_t)64 * K);
    cp16(&Ws[0][lrow * PAD + lcol], Wgp);
    cp16(&Ws[0][(lrow + 64) * PAD + lcol], Wgp + (size_t)64 * K);
    asm volatile("cp.async.commit_group;\n");

    for (int it = 0; it < nIter; ++it) {
        if (it + 1 < nIter) {
            const int nb = (it + 1) & 1, ko = (it + 1) * 16;
            cp16(&As[nb][lrow * PAD + lcol], Agp + ko);
            cp16(&As[nb][(lrow + 64) * PAD + lcol], Agp + (size_t)64 * K + ko);
            cp16(&Ws[nb][lrow * PAD + lcol], Wgp + ko);
            cp16(&Ws[nb][(lrow + 64) * PAD + lcol], Wgp + (size_t)64 * K + ko);
        }
        asm volatile("cp.async.commit_group;\n");
        asm volatile("cp.async.wait_group 1;\n");
        __syncthreads();
        const float* as = As[it & 1];
        const float* ws = Ws[it & 1];
#pragma unroll
        for (int kk = 0; kk < 16; kk += 8) {
            uint32_t a[4][4], b[4][2];
#pragma unroll
            for (int mt = 0; mt < 4; mt++) {
                const int mr = wm + mt * 16 + gid;
                const float2 pa = *reinterpret_cast<const float2*>(&as[mr * PAD + kk + 2 * tg]);
                const float2 pb = *reinterpret_cast<const float2*>(&as[(mr + 8) * PAD + kk + 2 * tg]);
                a[mt][0] = __float_as_uint(pa.x); a[mt][1] = __float_as_uint(pb.x);
                a[mt][2] = __float_as_uint(pa.y); a[mt][3] = __float_as_uint(pb.y);
            }
#pragma unroll
            for (int nt = 0; nt < 4; nt++) {
                const int nr = wn + nt * 8 + gid;
                const float2 pw = *reinterpret_cast<const float2*>(&ws[nr * PAD + kk + 2 * tg]);
                b[nt][0] = __float_as_uint(pw.x); b[nt][1] = __float_as_uint(pw.y);
            }
#pragma unroll
            for (int mt = 0; mt < 4; mt++)
#pragma unroll
                for (int nt = 0; nt < 4; nt++)
                    asm volatile(
                        "mma.sync.aligned.m16n8k8.row.col.f32.tf32.tf32.f32 "
                        "{%0,%1,%2,%3}, {%4,%5,%6,%7}, {%8,%9}, {%0,%1,%2,%3};\n"
                        : "+f"(acc[mt][nt][0]), "+f"(acc[mt][nt][1]),
                          "+f"(acc[mt][nt][2]), "+f"(acc[mt][nt][3])
                        : "r"(a[mt][0]), "r"(a[mt][1]), "r"(a[mt][2]), "r"(a[mt][3]),
                          "r"(b[nt][0]), "r"(b[nt][1]));
        }
        __syncthreads();
    }
#pragma unroll
    for (int mt = 0; mt < 4; mt++) {
        const int m = m0 + wm + mt * 16 + gid;
#pragma unroll
        for (int nt = 0; nt < 4; nt++) {
            const int o = o0 + wn + nt * 8 + tg * 2;
            const float b0 = bias[o], b1 = bias[o + 1];
            *reinterpret_cast<float2*>(&out[(size_t)m * O + o]) =
                make_float2(acc[mt][nt][0] + b0, acc[mt][nt][1] + b1);
            *reinterpret_cast<float2*>(&out[(size_t)(m + 8) * O + o]) =
                make_float2(acc[mt][nt][2] + b0, acc[mt][nt][3] + b1);
        }
    }
}

__global__ __launch_bounds__(256) void norm_rope2(
    const float* __restrict__ qd, const float* __restrict__ kd,
    const float* __restrict__ gqv, const float* __restrict__ gkv,
    const float* __restrict__ freqs, float scale)
{
    const int s = blockIdx.x, isK = blockIdx.y;
    const float* row = (isK ? kd : qd) + (size_t)s * DIM;
    __nv_bfloat16* dh = (isK ? g_kh : g_qh) + (size_t)s * DIM;
    __nv_bfloat16* dl = (isK ? g_kl : g_ql) + (size_t)s * DIM;
    const float* g = isK ? gkv : gqv;
    const int tid = threadIdx.x;

    float ss = 0.f;
    for (int c = tid; c < DIM; c += 256) { float v = row[c]; ss += v * v; }
#pragma unroll
    for (int off = 16; off; off >>= 1) ss += __shfl_xor_sync(~0u, ss, off);
    __shared__ float red[8];
    __shared__ float s_rms;
    if ((tid & 31) == 0) red[tid >> 5] = ss;
    __syncthreads();
    if (tid == 0) {
        float t = 0.f;
#pragma unroll
        for (int i = 0; i < 8; i++) t += red[i];
        s_rms = rsqrtf(t / (float)DIM + EPS_NORM);
    }
    __syncthreads();
    const float rms = s_rms;
    const int fidx = s / 576, rem = s % 576, hidx = rem / 24, widx = rem % 24;

    for (int p = tid; p < DIM / 2; p += 256) {
        const int n = p >> 6, m = p & 63;
        const int pos = (m < 22) ? fidx : (m < 43) ? hidx : widx;
        float sn, cs;
        sincosf(freqs[pos * 64 + m], &sn, &cs);
        const int c0 = n * HD + 2 * m;
        const float xr = row[c0] * rms * g[c0];
        const float xi = row[c0 + 1] * rms * g[c0 + 1];
        const float y0 = (xr * cs - xi * sn) * scale;
        const float y1 = (xr * sn + xi * cs) * scale;
        uint32_t hi, lo;
        split2(y0, y1, hi, lo);
        *reinterpret_cast<uint32_t*>(dh + c0) = hi;
        *reinterpret_cast<uint32_t*>(dl + c0) = lo;
    }
}

#define MMAB(C,A0,A1,A2,A3,B0,B1) \
    asm volatile("mma.sync.aligned.m16n8k16.row.col.f32.bf16.bf16.f32 " \
        "{%0,%1,%2,%3}, {%4,%5,%6,%7}, {%8,%9}, {%0,%1,%2,%3};\n" \
        : "+f"((C)[0]), "+f"((C)[1]), "+f"((C)[2]), "+f"((C)[3]) \
        : "r"(A0), "r"(A1), "r"(A2), "r"(A3), "r"(B0), "r"(B1))

#define SA_SMEM (16768 * 4)

__global__ __launch_bounds__(256) void stageA_mma()
{
    const int kb = blockIdx.x, f = blockIdx.y, h = blockIdx.z;
    extern __shared__ uint32_t smw[];
    uint32_t* KH = smw;
    uint32_t* KL = smw + 1632;
    uint32_t* VH = smw + 3264;
    uint32_t* VL = smw + 4896;
    uint32_t* TKH = smw + 6528;
    uint32_t* TKL = smw + 9088;
    uint32_t* TVH = smw + 11648;
    uint32_t* TVL = smw + 14208;

    const int tid = threadIdx.x, lane = tid & 31, w = tid >> 5;
    const int gid = lane >> 2, tg = lane & 3;
    const int skb = f * 576 + kb * 24;

    for (int idx = tid; idx < 24 * 64; idx += 256) {
        const int l = idx >> 6, wd = idx & 63;
        const size_t e = (size_t)(skb + l) * DIM + h * HD + wd * 2;
        KH[l * 68 + wd] = *reinterpret_cast<const uint32_t*>(g_kh + e);
        KL[l * 68 + wd] = *reinterpret_cast<const uint32_t*>(g_kl + e);
        VH[l * 68 + wd] = *reinterpret_cast<const uint32_t*>(g_vh + e);
        VL[l * 68 + wd] = *reinterpret_cast<const uint32_t*>(g_vl + e);
    }
    __syncthreads();
    {
        const ushort* sK = (const ushort*)KH;
        const ushort* sk = (const ushort*)KL;
        const ushort* sV = (const ushort*)VH;
        const ushort* sv = (const ushort*)VL;
        for (int idx = tid; idx < 128 * 12; idx += 256) {
            const int d = idx / 12, wv = idx % 12, l = 2 * wv;
            TKH[d * 20 + wv] = (uint32_t)sK[l * 136 + d] | ((uint32_t)sK[(l + 1) * 136 + d] << 16);
            TKL[d * 20 + wv] = (uint32_t)sk[l * 136 + d] | ((uint32_t)sk[(l + 1) * 136 + d] << 16);
            TVH[d * 20 + wv] = (uint32_t)sV[l * 136 + d] | ((uint32_t)sV[(l + 1) * 136 + d] << 16);
            TVL[d * 20 + wv] = (uint32_t)sv[l * 136 + d] | ((uint32_t)sv[(l + 1) * 136 + d] << 16);
        }
    }
    __syncthreads();

    for (int mt = w; mt < 18; mt += 8) {
        const int r0 = mt * 16 + gid, r1 = r0 + 8;
        const int a0i = r0 / 24, j0 = r0 - a0i * 24;
        const int a1i = r1 / 24, j1 = r1 - a1i * 24;
        const uint32_t* q0h = (const uint32_t*)(g_qh + (size_t)(a0i * 576 + kb * 24 + j0) * DIM + h * HD);
        const uint32_t* q0l = (const uint32_t*)(g_ql + (size_t)(a0i * 576 + kb * 24 + j0) * DIM + h * HD);
        const uint32_t* q1h = (const uint32_t*)(g_qh + (size_t)(a1i * 576 + kb * 24 + j1) * DIM + h * HD);
        const uint32_t* q1l = (const uint32_t*)(g_ql + (size_t)(a1i * 576 + kb * 24 + j1) * DIM + h * HD);

        float c[3][4];
#pragma unroll
        for (int nt = 0; nt < 3; nt++)
            c[nt][0] = c[nt][1] = c[nt][2] = c[nt][3] = 0.f;
#pragma unroll
        for (int kk = 0; kk < 8; kk++) {
            const int wa = kk * 8 + tg;
            const uint32_t ah0 = q0h[wa], ah1 = q1h[wa], ah2 = q0h[wa + 4], ah3 = q1h[wa + 4];
            const uint32_t al0 = q0l[wa], al1 = q1l[wa], al2 = q0l[wa + 4], al3 = q1l[wa + 4];
#pragma unroll
            for (int nt = 0; nt < 3; nt++) {
                const int nb = (nt * 8 + gid) * 68 + wa;
                const uint32_t bh0 = KH[nb], bh1 = KH[nb + 4];
                const uint32_t bl0 = KL[nb], bl1 = KL[nb + 4];
                MMAB(c[nt], ah0, ah1, ah2, ah3, bh0, bh1);
                MMAB(c[nt], ah0, ah1, ah2, ah3, bl0, bl1);
                MMAB(c[nt], al0, al1, al2, al3, bh0, bh1);
            }
        }

        float m0 = -1e30f, m1 = -1e30f;
#pragma unroll
        for (int nt = 0; nt < 3; nt++) {
#pragma unroll
            for (int r = 0; r < 4; r++) c[nt][r] *= CAPF;
            m0 = fmaxf(m0, fmaxf(c[nt][0], c[nt][1]));
            m1 = fmaxf(m1, fmaxf(c[nt][2], c[nt][3]));
        }
        m0 = fmaxf(m0, __shfl_xor_sync(~0u, m0, 1));
        m0 = fmaxf(m0, __shfl_xor_sync(~0u, m0, 2));
        m1 = fmaxf(m1, __shfl_xor_sync(~0u, m1, 1));
        m1 = fmaxf(m1, __shfl_xor_sync(~0u, m1, 2));
        float S0 = 0.f, E0 = 0.f, S1 = 0.f, E1 = 0.f, R[3][4];
#pragma unroll
        for (int nt = 0; nt < 3; nt++) {
            const float t0 = c[nt][0] - m0, t1 = c[nt][1] - m0;
            const float t2 = c[nt][2] - m1, t3 = c[nt][3] - m1;
            const float e0 = expf(t0), e1 = expf(t1), e2 = expf(t2), e3 = expf(t3);
            S0 += e0 + e1; E0 += e0 * t0 + e1 * t1;
            S1 += e2 + e3; E1 += e2 * t2 + e3 * t3;
            R[nt][0] = e0; R[nt][1] = e1; R[nt][2] = e2; R[nt][3] = e3;
        }
        S0 += __shfl_xor_sync(~0u, S0, 1); S0 += __shfl_xor_sync(~0u, S0, 2);
        E0 += __shfl_xor_sync(~0u, E0, 1); E0 += __shfl_xor_sync(~0u, E0, 2);
        S1 += __shfl_xor_sync(~0u, S1, 1); S1 += __shfl_xor_sync(~0u, S1, 2);
        E1 += __shfl_xor_sync(~0u, E1, 1); E1 += __shfl_xor_sync(~0u, E1, 2);
        const float i0 = 1.f / S0, i1 = 1.f / S1;

        const size_t rb0 = ((size_t)((h * 12 + a0i) * 24 + j0)) * FK + (f * 24 + kb);
        const size_t rb1 = ((size_t)((h * 12 + a1i) * 24 + j1)) * FK + (f * 24 + kb);
        if (tg == 0) {
            g_cL[rb0] = E0 * i0 - logf(S0);
            g_cL[rb1] = E1 * i1 - logf(S1);
        }

        uint32_t Ph[3], Pr[3], Ql[3], Qr[3];
#pragma unroll
        for (int nt = 0; nt < 3; nt++) {
            split2(R[nt][0] * i0, R[nt][1] * i0, Ph[nt], Ql[nt]);
            split2(R[nt][2] * i1, R[nt][3] * i1, Pr[nt], Qr[nt]);
        }

        const size_t wb0 = rb0 * 64, wb1 = rb1 * 64;
#pragma unroll
        for (int nt = 0; nt < 16; nt++) {
            const int nb = (nt * 8 + gid) * 20;
            float aa[4] = {0,0,0,0}, ay[4] = {0,0,0,0};
            uint32_t b0 = TKH[nb + tg], b1 = TKH[nb + 4 + tg];
            MMAB(aa, Ph[0], Pr[0], Ph[1], Pr[1], b0, b1);
            MMAB(aa, Ql[0], Qr[0], Ql[1], Qr[1], b0, b1);
            b0 = TKL[nb + tg]; b1 = TKL[nb + 4 + tg];
            MMAB(aa, Ph[0], Pr[0], Ph[1], Pr[1], b0, b1);
            b0 = TKH[nb + 8 + tg];
            MMAB(aa, Ph[2], Pr[2], 0u, 0u, b0, b0);
            MMAB(aa, Ql[2], Qr[2], 0u, 0u, b0, b0);
            b0 = TKL[nb + 8 + tg];
            MMAB(aa, Ph[2], Pr[2], 0u, 0u, b0, b0);

            b0 = TVH[nb + tg]; b1 = TVH[nb + 4 + tg];
            MMAB(ay, Ph[0], Pr[0], Ph[1], Pr[1], b0, b1);
            MMAB(ay, Ql[0], Qr[0], Ql[1], Qr[1], b0, b1);
            b0 = TVL[nb + tg]; b1 = TVL[nb + 4 + tg];
            MMAB(ay, Ph[0], Pr[0], Ph[1], Pr[1], b0, b1);
            b0 = TVH[nb + 8 + tg];
            MMAB(ay, Ph[2], Pr[2], 0u, 0u, b0, b0);
            MMAB(ay, Ql[2], Qr[2], 0u, 0u, b0, b0);
            b0 = TVL[nb + 8 + tg];
            MMAB(ay, Ph[2], Pr[2], 0u, 0u, b0, b0);

            const int wi = nt * 4 + tg;
            uint32_t hi, lo;
            split2(aa[0], aa[1], hi, lo);
            ((uint32_t*)g_ah)[wb0 + wi] = hi; ((uint32_t*)g_al)[wb0 + wi] = lo;
            split2(aa[2], aa[3], hi, lo);
            ((uint32_t*)g_ah)[wb1 + wi] = hi; ((uint32_t*)g_al)[wb1 + wi] = lo;
            split2(ay[0], ay[1], hi, lo);
            ((uint32_t*)g_yh)[wb0 + wi] = hi; ((uint32_t*)g_yl)[wb0 + wi] = lo;
            split2(ay[2], ay[3], hi, lo);
            ((uint32_t*)g_yh)[wb1 + wi] = hi; ((uint32_t*)g_yl)[wb1 + wi] = lo;
        }
    }
}

// ---------------- Stage B via bf16 split-3 MMA, 2 CTAs/SM --------------------
#define QHo 0
#define QLo 1632
#define CLo 3264
#define BLo 3552           // fp32 bL [24][292]
#define LmHo 10560         // packed [24][148]
#define LmLo 14112
#define Y0H 17664          // [32][68] per buffer
#define Y0L 19840
#define Y1H 22016
#define Y1L 24192
#define SB_SMEM (26368 * 4)   // 105,472 B -> 2 CTAs/SM

__global__ __launch_bounds__(256) void stageB_mma()
{
    const int j = blockIdx.x, a = blockIdx.y, h = blockIdx.z;
    extern __shared__ uint32_t smw[];
    uint32_t sb;
    asm("{ .reg .u64 t; cvta.to.shared.u64 t, %1; cvt.u32.u64 %0, t; }"
        : "=r"(sb) : "l"(smw));
    float* bl = (float*)(smw + BLo);
    float* cls = (float*)(smw + CLo);

    const int tid = threadIdx.x, lane = tid & 31, w = tid >> 5;
    const int gid = lane >> 2, tg = lane & 3;
    const size_t base = (size_t)(h * 12 + a) * 24 + j;
    const size_t albase = base * FK * HD;
    const size_t clbase = base * FK;

#define LOADY32(BH, BL2, C) do { \
    _Pragma("unroll") \
    for (int t5 = 0; t5 < 2; t5++) { \
        const int idx = tid + t5 * 256; \
        const int r = idx >> 4, seg = idx & 15; \
        const size_t so = albase + (size_t)((C) * 32 + r) * HD + seg * 8; \
        cp16s(sb + ((BH) + r * 68) * 4 + seg * 16, g_yh + so); \
        cp16s(sb + ((BL2) + r * 68) * 4 + seg * 16, g_yl + so); \
    } \
    asm volatile("cp.async.commit_group;\n"); \
} while (0)

    LOADY32(Y0H, Y0L, 0);

    // phase 0: Q hi/lo + cL
    for (int idx = tid; idx < 24 * 64; idx += 256) {
        const int i = idx >> 6, wd = idx & 63;
        const size_t e = (size_t)(a * 576 + i * 24 + j) * DIM + h * HD + wd * 2;
        smw[QHo + i * 68 + wd] = *reinterpret_cast<const uint32_t*>(g_qh + e);
        smw[QLo + i * 68 + wd] = *reinterpret_cast<const uint32_t*>(g_ql + e);
    }
    for (int idx = tid; idx < FK; idx += 256) cls[idx] = g_cL[clbase + idx];
    __syncthreads();

    // phase 1: bL = aL·Qᵀ − cL, stored transposed bl[i][fk]
    for (int mt = w; mt < 18; mt += 8) {
        const int fk0 = mt * 16 + gid, fk1 = fk0 + 8;
        const uint32_t* A0h = (const uint32_t*)g_ah + albase / 2 + fk0 * 64;
        const uint32_t* A0l = (const uint32_t*)g_al + albase / 2 + fk0 * 64;
        const uint32_t* A1h = (const uint32_t*)g_ah + albase / 2 + fk1 * 64;
        const uint32_t* A1l = (const uint32_t*)g_al + albase / 2 + fk1 * 64;

        float c[3][4];
#pragma unroll
        for (int nt = 0; nt < 3; nt++)
            c[nt][0] = c[nt][1] = c[nt][2] = c[nt][3] = 0.f;
#pragma unroll
        for (int kk = 0; kk < 8; kk++) {
            const int wa = kk * 8 + tg;
            const uint32_t ah0 = A0h[wa], ah1 = A1h[wa], ah2 = A0h[wa + 4], ah3 = A1h[wa + 4];
            const uint32_t al0 = A0l[wa], al1 = A1l[wa], al2 = A0l[wa + 4], al3 = A1l[wa + 4];
#pragma unroll
            for (int nt = 0; nt < 3; nt++) {
                const int nb = QHo + (nt * 8 + gid) * 68 + wa;
                const uint32_t bh0 = smw[nb], bh1 = smw[nb + 4];
                const uint32_t bl0 = smw[nb + (QLo - QHo)], bl1 = smw[nb + (QLo - QHo) + 4];
                MMAB(c[nt], ah0, ah1, ah2, ah3, bh0, bh1);
                MMAB(c[nt], ah0, ah1, ah2, ah3, bl0, bl1);
                MMAB(c[nt], al0, al1, al2, al3, bh0, bh1);
            }
        }
        const float cl0 = cls[fk0], cl1 = cls[fk1];
#pragma unroll
        for (int nt = 0; nt < 3; nt++) {
            const int i0 = nt * 8 + 2 * tg;
            bl[i0 * 292 + fk0]       = c[nt][0] - cl0;
            bl[(i0 + 1) * 292 + fk0] = c[nt][1] - cl0;
            bl[i0 * 292 + fk1]       = c[nt][2] - cl1;
            bl[(i0 + 1) * 292 + fk1] = c[nt][3] - cl1;
        }
    }
    __syncthreads();

    // phase 2: softmax over fk per i; pack Lm hi/lo
    for (int ri = w; ri < 24; ri += 8) {
        float* rowp = bl + ri * 292;
        float v[9], mx = -INFINITY;
#pragma unroll
        for (int q = 0; q < 9; q++) { v[q] = rowp[lane + q * 32]; mx = fmaxf(mx, v[q]); }
#pragma unroll
        for (int off = 16; off; off >>= 1) mx = fmaxf(mx, __shfl_xor_sync(~0u, mx, off));
        float s = 0.f;
#pragma unroll
        for (int q = 0; q < 9; q++) { v[q] = expf(v[q] - mx); s += v[q]; }
#pragma unroll
        for (int off = 16; off; off >>= 1) s += __shfl_xor_sync(~0u, s, off);
        const float inv = 1.f / s;
#pragma unroll
        for (int q = 0; q < 9; q++) rowp[lane + q * 32] = v[q] * inv;
        __syncwarp();
        for (int w2 = lane; w2 < 144; w2 += 32) {
            const float f0 = rowp[2 * w2], f1 = rowp[2 * w2 + 1];
            uint32_t hi, lo;
            split2(f0, f1, hi, lo);
            smw[LmHo + ri * 148 + w2] = hi;
            smw[LmLo + ri * 148 + w2] = lo;
        }
    }
    __syncthreads();

    // phase 3: out = Lmᵀ·Y over 9 chunks of 32 rows (double-buffered)
    float cc[2][2][4];
#pragma unroll
    for (int m = 0; m < 2; m++)
#pragma unroll
        for (int t = 0; t < 2; t++)
#pragma unroll
            for (int r = 0; r < 4; r++) cc[m][t][r] = 0.f;

#define YCHUNK32(BH, BL2, C) do { \
    _Pragma("unroll") \
    for (int kkl = 0; kkl < 2; kkl++) { \
        const int wa = ((C) * 2 + kkl) * 8 + tg; \
        uint32_t Ah[2][4], Al2[2][4]; \
        _Pragma("unroll") \
        for (int m = 0; m < 2; m++) { \
            int r2w = m * 16 + 8 + gid; if (r2w > 23) r2w = 23; \
            const int rb = (m * 16 + gid) * 148, rb8 = r2w * 148; \
            Ah[m][0] = smw[LmHo + rb + wa];     Ah[m][1] = smw[LmHo + rb8 + wa]; \
            Ah[m][2] = smw[LmHo + rb + wa + 4]; Ah[m][3] = smw[LmHo + rb8 + wa + 4]; \
            Al2[m][0] = smw[LmLo + rb + wa];     Al2[m][1] = smw[LmLo + rb8 + wa]; \
            Al2[m][2] = smw[LmLo + rb + wa + 4]; Al2[m][3] = smw[LmLo + rb8 + wa + 4]; \
        } \
        _Pragma("unroll") \
        for (int t = 0; t < 2; t++) { \
            const int nn = w * 2 + t; \
            const uint32_t ad = sb + ((BH) + (kkl * 16 + (lane & 15)) * 68 + nn * 4) * 4; \
            uint32_t bh0, bh1, bl0, bl1; \
            asm volatile("ldmatrix.sync.aligned.m8n8.x2.trans.shared.b16 {%0,%1}, [%2];" \
                : "=r"(bh0), "=r"(bh1) : "r"(ad)); \
            asm volatile("ldmatrix.sync.aligned.m8n8.x2.trans.shared.b16 {%0,%1}, [%2];" \
                : "=r"(bl0), "=r"(bl1) : "r"(ad + ((BL2) - (BH)) * 4)); \
            _Pragma("unroll") \
            for (int m = 0; m < 2; m++) { \
                MMAB(cc[m][t], Ah[m][0], Ah[m][1], Ah[m][2], Ah[m][3], bh0, bh1); \
                MMAB(cc[m][t], Al2[m][0], Al2[m][1], Al2[m][2], Al2[m][3], bh0, bh1); \
                MMAB(cc[m][t], Ah[m][0], Ah[m][1], Ah[m][2], Ah[m][3], bl0, bl1); \
            } \
        } \
    } \
} while (0)

    LOADY32(Y1H, Y1L, 1);
    for (int c = 0; c < 9; ++c) {
        if (c < 8) { asm volatile("cp.async.wait_group 1;\n"); }
        else       { asm volatile("cp.async.wait_group 0;\n"); }
        __syncthreads();
        if (c & 1) { YCHUNK32(Y1H, Y1L, c); } else { YCHUNK32(Y0H, Y0L, c); }
        __syncthreads();
        if (c + 2 < 9) {
            if (c & 1) { LOADY32(Y1H, Y1L, c + 2); } else { LOADY32(Y0H, Y0L, c + 2); }
        }
    }

    // stores: m-tile 0 rows gid, gid+8; m-tile 1 row 16+gid
#pragma unroll
    for (int t = 0; t < 2; t++) {
        const int d0 = (w * 2 + t) * 8 + 2 * tg;
        const size_t e0 = (size_t)(a * 576 + gid * 24 + j) * DIM + h * HD + d0;
        const size_t e1 = (size_t)(a * 576 + (gid + 8) * 24 + j) * DIM + h * HD + d0;
        const size_t e2 = (size_t)(a * 576 + (gid + 16) * 24 + j) * DIM + h * HD + d0;
        *reinterpret_cast<float2*>(&g_attn[e0]) = make_float2(cc[0][t][0], cc[0][t][1]);
        *reinterpret_cast<float2*>(&g_attn[e1]) = make_float2(cc[0][t][2], cc[0][t][3]);
        *reinterpret_cast<float2*>(&g_attn[e2]) = make_float2(cc[1][t][0], cc[1][t][1]);
    }
}

extern "C" void kernel_launch(void* const* d_in, const int* in_sizes, int n_in,
                              void* d_out, int out_size)
{
    (void)in_sizes; (void)n_in; (void)out_size;
    const float* x  = (const float*)d_in[0];
    const float* Wq = (const float*)d_in[1];
    const float* bq = (const float*)d_in[2];
    const float* Wk = (const float*)d_in[3];
    const float* bk = (const float*)d_in[4];
    const float* Wv = (const float*)d_in[5];
    const float* bv = (const float*)d_in[6];
    const float* Wo = (const float*)d_in[7];
    const float* bo = (const float*)d_in[8];
    const float* gq = (const float*)d_in[9];
    const float* gk = (const float*)d_in[10];
    const float* fr = (const float*)d_in[11];
    float* out = (float*)d_out;

    float *qp, *kp, *vp, *ap, *xr, *w4;
    cudaGetSymbolAddress((void**)&qp, g_q);
    cudaGetSymbolAddress((void**)&kp, g_k);
    cudaGetSymbolAddress((void**)&vp, g_v);
    cudaGetSymbolAddress((void**)&ap, g_attn);
    cudaGetSymbolAddress((void**)&xr, g_xr);
    cudaGetSymbolAddress((void**)&w4, g_w4);

    cudaFuncSetAttribute(stageA_mma,
        cudaFuncAttributeMaxDynamicSharedMemorySize, SA_SMEM);
    cudaFuncSetAttribute(stageB_mma,
        cudaFuncAttributeMaxDynamicSharedMemorySize, SB_SMEM);

    const int nx8 = SEQ * DIM / 8;
    const int nw8 = DIM * DIM / 8;
    const int WSZ = DIM * DIM;

    round_permute<<<(nx8 + 255) / 256, 256>>>(x, xr, nx8);
    round_permute_w4<<<dim3((nw8 + 255) / 256, 4), 256>>>(Wq, Wk, Wv, Wo, w4, nw8);

    const dim3 gg(DIM / 128, SEQ / 128);
    gemm_tf32p<<<gg, 256>>>(xr, w4 + 0 * WSZ, bq, qp, SEQ, DIM, DIM);
    gemm_tf32p<<<gg, 256>>>(xr, w4 + 1 * WSZ, bk, kp, SEQ, DIM, DIM);
    gemm_tf32p<<<gg, 256>>>(xr, w4 + 2 * WSZ, bv, vp, SEQ, DIM, DIM);

    const float s4 = powf((float)HD, -0.25f);
    norm_rope2<<<dim3(SEQ, 2), 256>>>(qp, kp, gq, gk, fr, s4);
    split_v<<<(SEQ * DIM / 2 + 255) / 256, 256>>>(SEQ * DIM / 2);

    stageA_mma<<<dim3(24, 12, 12), 256, SA_SMEM>>>();
    stageB_mma<<<dim3(24, 12, 12), 256, SB_SMEM>>>();

    round_permute<<<(nx8 + 255) / 256, 256>>>(ap, xr, nx8);
    gemm_tf32p<<<gg, 256>>>(xr, w4 + 3 * WSZ, bo, out, SEQ, DIM, DIM);
}